// round 4
// baseline (speedup 1.0000x reference)
#include <cuda_runtime.h>
#include <cuda_bf16.h>
#include <cstdint>

#define D_MODEL 1024
#define HEADS   16
#define DK      64
#define D_FF    4096
#define BB      2
#define SS      2048
#define NTOK    (BB * SS)        // 4096
#define LN_EPS  1e-6f
#define NEGV    (-1e9f)

// ---------------- scratch (device globals; no runtime allocation) -----------
__device__ float g_Q  [NTOK * D_MODEL];
__device__ float g_Kb [NTOK * D_MODEL];
__device__ float g_V  [NTOK * D_MODEL];
__device__ float g_ctx[NTOK * D_MODEL];
__device__ float g_t1 [NTOK * D_MODEL];
__device__ float g_x1 [NTOK * D_MODEL];
__device__ float g_h  [NTOK * D_FF];
__device__ float g_t2 [NTOK * D_MODEL];

#define EPI_BIAS  1
#define EPI_RELU  2
#define EPI_RESID 4

__device__ __forceinline__ uint32_t f2tf32(float x) {
    uint32_t y;
    asm("cvt.rna.tf32.f32 %0, %1;" : "=r"(y) : "f"(x));
    return y;
}

__device__ __forceinline__ void mma_tf32(float& c0, float& c1, float& c2, float& c3,
                                         uint32_t a0, uint32_t a1, uint32_t a2, uint32_t a3,
                                         uint32_t b0, uint32_t b1) {
    asm volatile(
        "mma.sync.aligned.m16n8k8.row.col.f32.tf32.tf32.f32 "
        "{%0,%1,%2,%3}, {%4,%5,%6,%7}, {%8,%9}, {%0,%1,%2,%3};"
        : "+f"(c0), "+f"(c1), "+f"(c2), "+f"(c3)
        : "r"(a0), "r"(a1), "r"(a2), "r"(a3), "r"(b0), "r"(b1));
}

// ---------------- tf32 tensor-core GEMM, double-buffered pipeline ------------
// C[m,n] = scale * sum_k A[m,k] * B[k,n]   (both row-major)
// Block 128x128x32, 8 warps of 64x32, m16n8k8 tf32 MMA.
// Per K-tile: LDG(next) -> MMA(cur) -> cvt+STS(next, other buffer) -> 1 sync.
#define ASZ (128 * 36)
#define BSZ (32 * 136)
#define GEMM_SMEM ((2 * (ASZ + BSZ)) * 4)

template<int EPI>
__global__ void __launch_bounds__(256)
tgemm_k(const float* __restrict__ A, const float* __restrict__ B,
        float* __restrict__ C, int M, int N, int K,
        int lda, int ldb, int ldc,
        float scale, const float* __restrict__ bias,
        const float* __restrict__ resid)
{
    extern __shared__ float sm[];
    float* Asb[2] = { sm, sm + ASZ };
    float* Bsb[2] = { sm + 2 * ASZ, sm + 2 * ASZ + BSZ };

    const int tid  = threadIdx.x;
    const int lane = tid & 31;
    const int wid  = tid >> 5;
    const int wm   = wid >> 2;
    const int wn   = wid & 3;
    const int gid  = lane >> 2;
    const int tig  = lane & 3;

    const int row0 = blockIdx.y * 128;
    const int col0 = blockIdx.x * 128;

    float acc[4][4][4];
#pragma unroll
    for (int mi = 0; mi < 4; mi++)
#pragma unroll
        for (int ni = 0; ni < 4; ni++)
#pragma unroll
            for (int r = 0; r < 4; r++) acc[mi][ni][r] = 0.f;

    int amf[4], akv[4], bkf[4], bnv[4];
#pragma unroll
    for (int i = 0; i < 4; i++) {
        int f = tid + i * 256;
        amf[i] = f >> 3;   akv[i] = (f & 7) * 4;
        bkf[i] = f >> 5;   bnv[i] = (f & 31) * 4;
    }

    const int nkt = K >> 5;
    float4 ra[4], rb[4];

    auto loadA = [&](int kt) {
        const int k0 = kt * 32;
#pragma unroll
        for (int i = 0; i < 4; i++)
            ra[i] = *(const float4*)&A[(long long)(row0 + amf[i]) * lda + k0 + akv[i]];
    };
    auto loadB = [&](int kt) {
        const int k0 = kt * 32;
#pragma unroll
        for (int i = 0; i < 4; i++) {
            int gn = col0 + bnv[i];
            rb[i] = (gn < N) ? *(const float4*)&B[(long long)(k0 + bkf[i]) * ldb + gn]
                             : make_float4(0.f, 0.f, 0.f, 0.f);
        }
    };
    auto storeAB = [&](int buf) {
        float* As = Asb[buf];
        float* Bs = Bsb[buf];
#pragma unroll
        for (int i = 0; i < 4; i++) {
            float4 v = ra[i];
            v.x = __uint_as_float(f2tf32(v.x));
            v.y = __uint_as_float(f2tf32(v.y));
            v.z = __uint_as_float(f2tf32(v.z));
            v.w = __uint_as_float(f2tf32(v.w));
            *(float4*)&As[amf[i] * 36 + akv[i]] = v;
            float4 u = rb[i];
            u.x = __uint_as_float(f2tf32(u.x));
            u.y = __uint_as_float(f2tf32(u.y));
            u.z = __uint_as_float(f2tf32(u.z));
            u.w = __uint_as_float(f2tf32(u.w));
            *(float4*)&Bs[bkf[i] * 136 + bnv[i]] = u;
        }
    };

    loadA(0); loadB(0);
    storeAB(0);
    __syncthreads();

    for (int kt = 0; kt < nkt; kt++) {
        const int cur = kt & 1;
        const bool more = (kt + 1 < nkt);
        if (more) { loadA(kt + 1); loadB(kt + 1); }   // LDG hidden under MMAs

        const uint32_t* Asu = (const uint32_t*)Asb[cur];
        const uint32_t* Bsu = (const uint32_t*)Bsb[cur];
#pragma unroll
        for (int ks = 0; ks < 4; ks++) {
            const int k = ks * 8;
            uint32_t af[4][4], bf[4][2];
#pragma unroll
            for (int mi = 0; mi < 4; mi++) {
                int m = wm * 64 + mi * 16 + gid;
                af[mi][0] = Asu[m * 36 + k + tig];
                af[mi][1] = Asu[(m + 8) * 36 + k + tig];
                af[mi][2] = Asu[m * 36 + k + tig + 4];
                af[mi][3] = Asu[(m + 8) * 36 + k + tig + 4];
            }
#pragma unroll
            for (int ni = 0; ni < 4; ni++) {
                int n = wn * 32 + ni * 8 + gid;
                bf[ni][0] = Bsu[(k + tig) * 136 + n];
                bf[ni][1] = Bsu[(k + tig + 4) * 136 + n];
            }
#pragma unroll
            for (int mi = 0; mi < 4; mi++)
#pragma unroll
                for (int ni = 0; ni < 4; ni++)
                    mma_tf32(acc[mi][ni][0], acc[mi][ni][1], acc[mi][ni][2], acc[mi][ni][3],
                             af[mi][0], af[mi][1], af[mi][2], af[mi][3],
                             bf[ni][0], bf[ni][1]);
        }

        if (more) storeAB(cur ^ 1);    // STS into other buffer, overlaps late warps
        __syncthreads();               // single barrier per K-tile
    }

    // ---- epilogue ----
#pragma unroll
    for (int mi = 0; mi < 4; mi++) {
#pragma unroll
        for (int ni = 0; ni < 4; ni++) {
            int r0 = row0 + wm * 64 + mi * 16 + gid;
            int cb = col0 + wn * 32 + ni * 8 + tig * 2;
            if (cb >= N) continue;
#pragma unroll
            for (int half = 0; half < 2; half++) {
                int rr = r0 + half * 8;
                float v0 = acc[mi][ni][half * 2 + 0] * scale;
                float v1 = acc[mi][ni][half * 2 + 1] * scale;
                if (EPI & EPI_BIAS)  { v0 += bias[cb]; v1 += bias[cb + 1]; }
                if (EPI & EPI_RESID) {
                    const float2 rv = *(const float2*)&resid[(long long)rr * ldc + cb];
                    v0 += rv.x; v1 += rv.y;
                }
                if (EPI & EPI_RELU)  { v0 = fmaxf(v0, 0.f); v1 = fmaxf(v1, 0.f); }
                *(float2*)&C[(long long)rr * ldc + cb] = make_float2(v0, v1);
            }
        }
    }
}

// ---------------- fused flash attention --------------------------------------
// CTA: 128 queries of one (b,h). 8 warps x 16 query rows. KV tiles of 64 keys.
#define FA_SMEM ((128*68 + 64*68 + 64*72 + 128*68) * 4 + 256)

__global__ void __launch_bounds__(256, 2)
fa_k(const float* __restrict__ Q, const float* __restrict__ K,
     const float* __restrict__ V, const int* __restrict__ mask,
     float* __restrict__ O)
{
    extern __shared__ float sm[];
    float* Qs = sm;                         // 128*68
    float* Ks = Qs + 128 * 68;              // 64*68
    float* Vs = Ks + 64 * 68;               // 64*72
    float* Ps = Vs + 64 * 72;               // 128*68
    int*   Ms = (int*)(Ps + 128 * 68);      // 64

    const int qt  = blockIdx.x;
    const int z   = blockIdx.y;
    const int b   = z >> 4, h = z & 15;
    const int tid = threadIdx.x, lane = tid & 31, w = tid >> 5;
    const int gid = lane >> 2, tig = lane & 3;

    const long long base = ((long long)b * SS) * D_MODEL + h * DK;
    const float* Qg = Q + base + (long long)qt * 128 * D_MODEL;
    const float* Kg = K + base;
    const float* Vg = V + base;
    const int*   mg = mask + (long long)b * SS;

#pragma unroll
    for (int i = 0; i < 8; i++) {
        int idx = tid + i * 256;
        int r = idx >> 4, c = (idx & 15) * 4;
        float4 v = *(const float4*)&Qg[(long long)r * D_MODEL + c];
        v.x = __uint_as_float(f2tf32(v.x * 0.125f));
        v.y = __uint_as_float(f2tf32(v.y * 0.125f));
        v.z = __uint_as_float(f2tf32(v.z * 0.125f));
        v.w = __uint_as_float(f2tf32(v.w * 0.125f));
        *(float4*)&Qs[r * 68 + c] = v;
    }

    float m0 = -INFINITY, m1 = -INFINITY;
    float l0 = 0.f, l1 = 0.f;
    float oacc[8][4];
#pragma unroll
    for (int ng = 0; ng < 8; ng++)
#pragma unroll
        for (int r = 0; r < 4; r++) oacc[ng][r] = 0.f;

    const uint32_t* Qsu = (const uint32_t*)Qs;
    const uint32_t* Ksu = (const uint32_t*)Ks;
    const uint32_t* Vsu = (const uint32_t*)Vs;
    const uint32_t* Psu = (const uint32_t*)Ps;
    const int qrow = w * 16 + gid;

    for (int kt = 0; kt < SS / 64; kt++) {
        __syncthreads();
#pragma unroll
        for (int i = 0; i < 4; i++) {
            int idx = tid + i * 256;
            int r = idx >> 4, c = (idx & 15) * 4;
            long long go = (long long)(kt * 64 + r) * D_MODEL + c;
            float4 kv = *(const float4*)&Kg[go];
            kv.x = __uint_as_float(f2tf32(kv.x));
            kv.y = __uint_as_float(f2tf32(kv.y));
            kv.z = __uint_as_float(f2tf32(kv.z));
            kv.w = __uint_as_float(f2tf32(kv.w));
            *(float4*)&Ks[r * 68 + c] = kv;
            float4 vv = *(const float4*)&Vg[go];
            vv.x = __uint_as_float(f2tf32(vv.x));
            vv.y = __uint_as_float(f2tf32(vv.y));
            vv.z = __uint_as_float(f2tf32(vv.z));
            vv.w = __uint_as_float(f2tf32(vv.w));
            *(float4*)&Vs[r * 72 + c] = vv;
        }
        if (tid < 64) Ms[tid] = mg[kt * 64 + tid];
        __syncthreads();

        float s[8][4];
#pragma unroll
        for (int ni = 0; ni < 8; ni++)
#pragma unroll
            for (int r = 0; r < 4; r++) s[ni][r] = 0.f;

#pragma unroll
        for (int kg = 0; kg < 8; kg++) {
            const int k = kg * 8;
            uint32_t a0 = Qsu[qrow * 68 + k + tig];
            uint32_t a1 = Qsu[(qrow + 8) * 68 + k + tig];
            uint32_t a2 = Qsu[qrow * 68 + k + tig + 4];
            uint32_t a3 = Qsu[(qrow + 8) * 68 + k + tig + 4];
#pragma unroll
            for (int ni = 0; ni < 8; ni++) {
                uint32_t b0 = Ksu[(ni * 8 + gid) * 68 + k + tig];
                uint32_t b1 = Ksu[(ni * 8 + gid) * 68 + k + tig + 4];
                mma_tf32(s[ni][0], s[ni][1], s[ni][2], s[ni][3], a0, a1, a2, a3, b0, b1);
            }
        }

        float tm0 = -3.0e38f, tm1 = -3.0e38f;
#pragma unroll
        for (int ni = 0; ni < 8; ni++) {
            int c0 = ni * 8 + tig * 2;
            if (Ms[c0] == 0)     { s[ni][0] = NEGV; s[ni][2] = NEGV; }
            if (Ms[c0 + 1] == 0) { s[ni][1] = NEGV; s[ni][3] = NEGV; }
            tm0 = fmaxf(tm0, fmaxf(s[ni][0], s[ni][1]));
            tm1 = fmaxf(tm1, fmaxf(s[ni][2], s[ni][3]));
        }
        tm0 = fmaxf(tm0, __shfl_xor_sync(0xffffffffu, tm0, 1));
        tm0 = fmaxf(tm0, __shfl_xor_sync(0xffffffffu, tm0, 2));
        tm1 = fmaxf(tm1, __shfl_xor_sync(0xffffffffu, tm1, 1));
        tm1 = fmaxf(tm1, __shfl_xor_sync(0xffffffffu, tm1, 2));

        float mn0 = fmaxf(m0, tm0), mn1 = fmaxf(m1, tm1);
        float cr0 = __expf(m0 - mn0), cr1 = __expf(m1 - mn1);

        float sum0 = 0.f, sum1 = 0.f;
#pragma unroll
        for (int ni = 0; ni < 8; ni++) {
            float p0 = __expf(s[ni][0] - mn0);
            float p1 = __expf(s[ni][1] - mn0);
            float p2 = __expf(s[ni][2] - mn1);
            float p3 = __expf(s[ni][3] - mn1);
            sum0 += p0 + p1; sum1 += p2 + p3;
            float2 lo, hi;
            lo.x = __uint_as_float(f2tf32(p0)); lo.y = __uint_as_float(f2tf32(p1));
            hi.x = __uint_as_float(f2tf32(p2)); hi.y = __uint_as_float(f2tf32(p3));
            *(float2*)&Ps[qrow * 68 + ni * 8 + tig * 2] = lo;
            *(float2*)&Ps[(qrow + 8) * 68 + ni * 8 + tig * 2] = hi;
        }
        sum0 += __shfl_xor_sync(0xffffffffu, sum0, 1);
        sum0 += __shfl_xor_sync(0xffffffffu, sum0, 2);
        sum1 += __shfl_xor_sync(0xffffffffu, sum1, 1);
        sum1 += __shfl_xor_sync(0xffffffffu, sum1, 2);

        l0 = l0 * cr0 + sum0;
        l1 = l1 * cr1 + sum1;
        m0 = mn0; m1 = mn1;

#pragma unroll
        for (int ng = 0; ng < 8; ng++) {
            oacc[ng][0] *= cr0; oacc[ng][1] *= cr0;
            oacc[ng][2] *= cr1; oacc[ng][3] *= cr1;
        }
        __syncwarp();

#pragma unroll
        for (int kg = 0; kg < 8; kg++) {
            const int k = kg * 8;
            uint32_t a0 = Psu[qrow * 68 + k + tig];
            uint32_t a1 = Psu[(qrow + 8) * 68 + k + tig];
            uint32_t a2 = Psu[qrow * 68 + k + tig + 4];
            uint32_t a3 = Psu[(qrow + 8) * 68 + k + tig + 4];
#pragma unroll
            for (int ng = 0; ng < 8; ng++) {
                uint32_t b0 = Vsu[(k + tig) * 72 + ng * 8 + gid];
                uint32_t b1 = Vsu[(k + tig + 4) * 72 + ng * 8 + gid];
                mma_tf32(oacc[ng][0], oacc[ng][1], oacc[ng][2], oacc[ng][3],
                         a0, a1, a2, a3, b0, b1);
            }
        }
    }

    float inv0 = 1.0f / l0, inv1 = 1.0f / l1;
    float* Og = O + base + (long long)qt * 128 * D_MODEL;
#pragma unroll
    for (int ng = 0; ng < 8; ng++) {
        int c = ng * 8 + tig * 2;
        *(float2*)&Og[(long long)qrow * D_MODEL + c] =
            make_float2(oacc[ng][0] * inv0, oacc[ng][1] * inv0);
        *(float2*)&Og[(long long)(qrow + 8) * D_MODEL + c] =
            make_float2(oacc[ng][2] * inv1, oacc[ng][3] * inv1);
    }
}

// ---------------- LayerNorm (ddof=1, /(std+eps)) -----------------------------
__global__ void __launch_bounds__(256)
ln_k(const float* __restrict__ in, float* __restrict__ out,
     const float* __restrict__ alpha, const float* __restrict__ beta)
{
    const long long row = blockIdx.x;
    const float* p = in + row * D_MODEL;
    float* o = out + row * D_MODEL;
    const int tid = threadIdx.x;

    float4 x4 = ((const float4*)p)[tid];
    float s  = x4.x + x4.y + x4.z + x4.w;
    float sq = x4.x*x4.x + x4.y*x4.y + x4.z*x4.z + x4.w*x4.w;

    __shared__ float rs[256], rq[256];
    rs[tid] = s; rq[tid] = sq; __syncthreads();
    for (int st = 128; st > 0; st >>= 1) {
        if (tid < st) { rs[tid] += rs[tid + st]; rq[tid] += rq[tid + st]; }
        __syncthreads();
    }
    float mean = rs[0] * (1.0f / D_MODEL);
    float var  = (rq[0] - rs[0] * mean) * (1.0f / (D_MODEL - 1));
    var = fmaxf(var, 0.f);
    float inv = 1.0f / (sqrtf(var) + LN_EPS);

    float4 a4 = ((const float4*)alpha)[tid];
    float4 b4 = ((const float4*)beta)[tid];
    float4 o4;
    o4.x = a4.x * (x4.x - mean) * inv + b4.x;
    o4.y = a4.y * (x4.y - mean) * inv + b4.y;
    o4.z = a4.z * (x4.z - mean) * inv + b4.z;
    o4.w = a4.w * (x4.w - mean) * inv + b4.w;
    ((float4*)o)[tid] = o4;
}

// ---------------- launcher ---------------------------------------------------
extern "C" void kernel_launch(void* const* d_in, const int* in_sizes, int n_in,
                              void* d_out, int out_size)
{
    const float* x     = (const float*)d_in[0];
    const int*   mask  = (const int*)  d_in[1];
    const float* w_q   = (const float*)d_in[2];
    const float* w_k   = (const float*)d_in[3];
    const float* w_v   = (const float*)d_in[4];
    const float* w_o   = (const float*)d_in[5];
    const float* W1    = (const float*)d_in[6];
    const float* b1    = (const float*)d_in[7];
    const float* W2    = (const float*)d_in[8];
    const float* b2    = (const float*)d_in[9];
    const float* al1   = (const float*)d_in[10];
    const float* be1   = (const float*)d_in[11];
    const float* al2   = (const float*)d_in[12];
    const float* be2   = (const float*)d_in[13];
    float* out = (float*)d_out;

    float *Q, *Kb, *V, *CTX, *T1, *X1, *H, *T2;
    cudaGetSymbolAddress((void**)&Q,   g_Q);
    cudaGetSymbolAddress((void**)&Kb,  g_Kb);
    cudaGetSymbolAddress((void**)&V,   g_V);
    cudaGetSymbolAddress((void**)&CTX, g_ctx);
    cudaGetSymbolAddress((void**)&T1,  g_t1);
    cudaGetSymbolAddress((void**)&X1,  g_x1);
    cudaGetSymbolAddress((void**)&H,   g_h);
    cudaGetSymbolAddress((void**)&T2,  g_t2);

    cudaFuncSetAttribute(fa_k, cudaFuncAttributeMaxDynamicSharedMemorySize, FA_SMEM);
    cudaFuncSetAttribute(tgemm_k<0>, cudaFuncAttributeMaxDynamicSharedMemorySize, GEMM_SMEM);
    cudaFuncSetAttribute(tgemm_k<EPI_RESID>, cudaFuncAttributeMaxDynamicSharedMemorySize, GEMM_SMEM);
    cudaFuncSetAttribute(tgemm_k<EPI_BIAS|EPI_RELU>, cudaFuncAttributeMaxDynamicSharedMemorySize, GEMM_SMEM);
    cudaFuncSetAttribute(tgemm_k<EPI_BIAS|EPI_RESID>, cudaFuncAttributeMaxDynamicSharedMemorySize, GEMM_SMEM);

    const dim3 blk(256);
    auto grd = [](int N, int M) {
        return dim3((unsigned)((N + 127) / 128), (unsigned)((M + 127) / 128), 1);
    };

    // 1-3: Q/K/V projections  [4096,1024] = x @ w
    tgemm_k<0><<<grd(D_MODEL, NTOK), blk, GEMM_SMEM>>>(x, w_q, Q,  NTOK, D_MODEL, D_MODEL,
        D_MODEL, D_MODEL, D_MODEL, 1.f, nullptr, nullptr);
    tgemm_k<0><<<grd(D_MODEL, NTOK), blk, GEMM_SMEM>>>(x, w_k, Kb, NTOK, D_MODEL, D_MODEL,
        D_MODEL, D_MODEL, D_MODEL, 1.f, nullptr, nullptr);
    tgemm_k<0><<<grd(D_MODEL, NTOK), blk, GEMM_SMEM>>>(x, w_v, V,  NTOK, D_MODEL, D_MODEL,
        D_MODEL, D_MODEL, D_MODEL, 1.f, nullptr, nullptr);

    // 4: fused attention (QK^T/8 -> mask -> softmax -> @V), writes ctx
    fa_k<<<dim3(SS / 128, BB * HEADS), blk, FA_SMEM>>>(Q, Kb, V, mask, CTX);

    // 5: t1 = ctx @ w_o + x  (residual)
    tgemm_k<EPI_RESID><<<grd(D_MODEL, NTOK), blk, GEMM_SMEM>>>(CTX, w_o, T1, NTOK, D_MODEL, D_MODEL,
        D_MODEL, D_MODEL, D_MODEL, 1.f, nullptr, x);

    // 6: x1 = LN1(t1)
    ln_k<<<NTOK, blk>>>(T1, X1, al1, be1);

    // 7: h = relu(x1 @ W1 + b1)
    tgemm_k<EPI_BIAS|EPI_RELU><<<grd(D_FF, NTOK), blk, GEMM_SMEM>>>(X1, W1, H, NTOK, D_FF, D_MODEL,
        D_MODEL, D_FF, D_FF, 1.f, b1, nullptr);

    // 8: t2 = h @ W2 + b2 + x1 (residual)
    tgemm_k<EPI_BIAS|EPI_RESID><<<grd(D_MODEL, NTOK), blk, GEMM_SMEM>>>(H, W2, T2, NTOK, D_MODEL, D_FF,
        D_FF, D_MODEL, D_MODEL, 1.f, b2, X1);

    // 9: out = LN2(t2)
    ln_k<<<NTOK, blk>>>(T2, out, al2, be2);
}

// round 7
// speedup vs baseline: 1.7758x; 1.7758x over previous
#include <cuda_runtime.h>
#include <cuda_bf16.h>
#include <cstdint>

#define D_MODEL 1024
#define HEADS   16
#define DK      64
#define D_FF    4096
#define BB      2
#define SS      2048
#define NTOK    (BB * SS)        // 4096
#define LN_EPS  1e-6f
#define NEGV    (-1e9f)

// ---------------- scratch (device globals; no runtime allocation) -----------
__device__ float g_Q  [NTOK * D_MODEL];
__device__ float g_Kb [NTOK * D_MODEL];
__device__ float g_V  [NTOK * D_MODEL];
__device__ float g_ctx[NTOK * D_MODEL];
__device__ float g_t1 [NTOK * D_MODEL];
__device__ float g_x1 [NTOK * D_MODEL];
__device__ float g_h  [NTOK * D_FF];
__device__ float g_t2 [NTOK * D_MODEL];
// tf32-rounded operand copies
__device__ float g_xr [NTOK * D_MODEL];
__device__ float g_wqr[D_MODEL * D_MODEL];
__device__ float g_wkr[D_MODEL * D_MODEL];
__device__ float g_wvr[D_MODEL * D_MODEL];
__device__ float g_wor[D_MODEL * D_MODEL];
__device__ float g_W1r[D_MODEL * D_FF];
__device__ float g_W2r[D_FF * D_MODEL];

#define EPI_BIAS  1
#define EPI_RELU  2
#define EPI_RESID 4
#define EPI_TF32  8

__device__ __forceinline__ uint32_t f2tf32(float x) {
    uint32_t y;
    asm("cvt.rna.tf32.f32 %0, %1;" : "=r"(y) : "f"(x));
    return y;
}
__device__ __forceinline__ float rtf(float x) { return __uint_as_float(f2tf32(x)); }

__device__ __forceinline__ void mma_tf32(float& c0, float& c1, float& c2, float& c3,
                                         uint32_t a0, uint32_t a1, uint32_t a2, uint32_t a3,
                                         uint32_t b0, uint32_t b1) {
    asm volatile(
        "mma.sync.aligned.m16n8k8.row.col.f32.tf32.tf32.f32 "
        "{%0,%1,%2,%3}, {%4,%5,%6,%7}, {%8,%9}, {%0,%1,%2,%3};"
        : "+f"(c0), "+f"(c1), "+f"(c2), "+f"(c3)
        : "r"(a0), "r"(a1), "r"(a2), "r"(a3), "r"(b0), "r"(b1));
}

__device__ __forceinline__ void cp16(uint32_t saddr, const void* gaddr) {
    asm volatile("cp.async.cg.shared.global [%0], [%1], 16;" :: "r"(saddr), "l"(gaddr));
}
__device__ __forceinline__ void cp_commit() {
    asm volatile("cp.async.commit_group;");
}
template<int N> __device__ __forceinline__ void cp_wait() {
    asm volatile("cp.async.wait_group %0;" :: "n"(N));
}

// ---------------- tf32 rounding pass (operand prep) --------------------------
__global__ void __launch_bounds__(256)
rnd_k(const float* __restrict__ in, float* __restrict__ out, int n4)
{
    int i = blockIdx.x * 256 + threadIdx.x;
    if (i >= n4) return;
    float4 v = ((const float4*)in)[i];
    v.x = rtf(v.x); v.y = rtf(v.y); v.z = rtf(v.z); v.w = rtf(v.w);
    ((float4*)out)[i] = v;
}

// ---------------- tf32 tensor-core GEMM, 3-stage cp.async pipeline -----------
// C[m,n] = scale * sum_k A[m,k] * B[k,n]  (row-major, operands pre-rounded tf32)
// Block tile 128x128x32, 8 warps of 64x32. M,N multiples of 128; K multiple of 64.
#define STAGES 3
#define ASZ (128 * 36)
#define BSZ (32 * 136)
#define STG (ASZ + BSZ)
#define GEMM_SMEM (STAGES * STG * 4)

template<int EPI>
__global__ void __launch_bounds__(256, 2)
tgemm_k(const float* __restrict__ A, const float* __restrict__ B,
        float* __restrict__ C, int N, int K,
        int lda, int ldb, int ldc,
        float scale, const float* __restrict__ bias,
        const float* __restrict__ resid)
{
    extern __shared__ float sm[];
    const int tid  = threadIdx.x;
    const int lane = tid & 31;
    const int wid  = tid >> 5;
    const int wm   = wid >> 2;
    const int wn   = wid & 3;
    const int gid  = lane >> 2;
    const int tig  = lane & 3;

    const int row0 = blockIdx.y * 128;
    const int col0 = blockIdx.x * 128;

    int amf[4], akv[4], bkf[4], bnv[4];
#pragma unroll
    for (int i = 0; i < 4; i++) {
        int f = tid + i * 256;
        amf[i] = f >> 3;   akv[i] = (f & 7) * 4;
        bkf[i] = f >> 5;   bnv[i] = (f & 31) * 4;
    }

    const uint32_t smb = (uint32_t)__cvta_generic_to_shared(sm);
    const int nkt = K >> 5;

    auto issue = [&](int kt) {
        const int buf = kt % STAGES;
        const uint32_t as = smb + (uint32_t)(buf * STG) * 4u;
        const uint32_t bs = as + (uint32_t)ASZ * 4u;
        const int k0 = kt * 32;
#pragma unroll
        for (int i = 0; i < 4; i++) {
            cp16(as + (uint32_t)(amf[i] * 36 + akv[i]) * 4u,
                 &A[(long long)(row0 + amf[i]) * lda + k0 + akv[i]]);
            cp16(bs + (uint32_t)(bkf[i] * 136 + bnv[i]) * 4u,
                 &B[(long long)(k0 + bkf[i]) * ldb + col0 + bnv[i]]);
        }
        cp_commit();
    };

    issue(0); issue(1);              // K >= 64 at every call site

    float acc[4][4][4];
#pragma unroll
    for (int mi = 0; mi < 4; mi++)
#pragma unroll
        for (int ni = 0; ni < 4; ni++)
#pragma unroll
            for (int r = 0; r < 4; r++) acc[mi][ni][r] = 0.f;

    for (int kt = 0; kt < nkt; kt++) {
        // Tail fix: at kt == nkt-1 only 1 group is pending (tile kt itself),
        // so wait_group<1> would NOT guarantee it landed. Drain fully there.
        if (kt + 1 < nkt) cp_wait<1>();
        else              cp_wait<0>();
        __syncthreads();             // everyone's copies visible

        const uint32_t* Asu = (const uint32_t*)(sm + (kt % STAGES) * STG);
        const uint32_t* Bsu = Asu + ASZ;
#pragma unroll
        for (int ks = 0; ks < 4; ks++) {
            const int k = ks * 8;
            uint32_t af[4][4], bf[4][2];
#pragma unroll
            for (int mi = 0; mi < 4; mi++) {
                int m = wm * 64 + mi * 16 + gid;
                af[mi][0] = Asu[m * 36 + k + tig];
                af[mi][1] = Asu[(m + 8) * 36 + k + tig];
                af[mi][2] = Asu[m * 36 + k + tig + 4];
                af[mi][3] = Asu[(m + 8) * 36 + k + tig + 4];
            }
#pragma unroll
            for (int ni = 0; ni < 4; ni++) {
                int n = wn * 32 + ni * 8 + gid;
                bf[ni][0] = Bsu[(k + tig) * 136 + n];
                bf[ni][1] = Bsu[(k + tig + 4) * 136 + n];
            }
#pragma unroll
            for (int mi = 0; mi < 4; mi++)
#pragma unroll
                for (int ni = 0; ni < 4; ni++)
                    mma_tf32(acc[mi][ni][0], acc[mi][ni][1], acc[mi][ni][2], acc[mi][ni][3],
                             af[mi][0], af[mi][1], af[mi][2], af[mi][3],
                             bf[ni][0], bf[ni][1]);
        }
        if (kt + 2 < nkt) issue(kt + 2);   // writes buffer last read at kt-1: safe
    }

    // ---- epilogue ----
#pragma unroll
    for (int mi = 0; mi < 4; mi++) {
#pragma unroll
        for (int ni = 0; ni < 4; ni++) {
            int r0 = row0 + wm * 64 + mi * 16 + gid;
            int cb = col0 + wn * 32 + ni * 8 + tig * 2;
#pragma unroll
            for (int half = 0; half < 2; half++) {
                int rr = r0 + half * 8;
                float v0 = acc[mi][ni][half * 2 + 0] * scale;
                float v1 = acc[mi][ni][half * 2 + 1] * scale;
                if (EPI & EPI_BIAS)  { v0 += bias[cb]; v1 += bias[cb + 1]; }
                if (EPI & EPI_RESID) {
                    const float2 rv = *(const float2*)&resid[(long long)rr * ldc + cb];
                    v0 += rv.x; v1 += rv.y;
                }
                if (EPI & EPI_RELU)  { v0 = fmaxf(v0, 0.f); v1 = fmaxf(v1, 0.f); }
                if (EPI & EPI_TF32)  { v0 = rtf(v0); v1 = rtf(v1); }
                *(float2*)&C[(long long)rr * ldc + cb] = make_float2(v0, v1);
            }
        }
    }
}

// ---------------- fused flash attention --------------------------------------
// CTA: 128 queries of one (b,h). 8 warps x 16 query rows. KV tiles of 64 keys.
// Q pre-scaled by 0.125 and tf32-rounded; K/V tf32-rounded (GEMM epilogue).
#define FA_SMEM ((128*68 + 64*68 + 64*72 + 128*68) * 4 + 256)

__global__ void __launch_bounds__(256, 2)
fa_k(const float* __restrict__ Q, const float* __restrict__ K,
     const float* __restrict__ V, const int* __restrict__ mask,
     float* __restrict__ O)
{
    extern __shared__ float sm[];
    float* Qs = sm;                         // 128*68
    float* Ks = Qs + 128 * 68;              // 64*68
    float* Vs = Ks + 64 * 68;               // 64*72
    float* Ps = Vs + 64 * 72;               // 128*68
    int*   Ms = (int*)(Ps + 128 * 68);      // 64

    const int qt  = blockIdx.x;
    const int z   = blockIdx.y;
    const int b   = z >> 4, h = z & 15;
    const int tid = threadIdx.x, lane = tid & 31, w = tid >> 5;
    const int gid = lane >> 2, tig = lane & 3;

    const long long base = ((long long)b * SS) * D_MODEL + h * DK;
    const float* Qg = Q + base + (long long)qt * 128 * D_MODEL;
    const float* Kg = K + base;
    const float* Vg = V + base;
    const int*   mg = mask + (long long)b * SS;

#pragma unroll
    for (int i = 0; i < 8; i++) {
        int idx = tid + i * 256;
        int r = idx >> 4, c = (idx & 15) * 4;
        *(float4*)&Qs[r * 68 + c] = *(const float4*)&Qg[(long long)r * D_MODEL + c];
    }

    float m0 = -INFINITY, m1 = -INFINITY;
    float l0 = 0.f, l1 = 0.f;
    float oacc[8][4];
#pragma unroll
    for (int ng = 0; ng < 8; ng++)
#pragma unroll
        for (int r = 0; r < 4; r++) oacc[ng][r] = 0.f;

    const uint32_t* Qsu = (const uint32_t*)Qs;
    const uint32_t* Ksu = (const uint32_t*)Ks;
    const uint32_t* Vsu = (const uint32_t*)Vs;
    const uint32_t* Psu = (const uint32_t*)Ps;
    const int qrow = w * 16 + gid;

    for (int kt = 0; kt < SS / 64; kt++) {
        __syncthreads();
#pragma unroll
        for (int i = 0; i < 4; i++) {
            int idx = tid + i * 256;
            int r = idx >> 4, c = (idx & 15) * 4;
            long long go = (long long)(kt * 64 + r) * D_MODEL + c;
            *(float4*)&Ks[r * 68 + c] = *(const float4*)&Kg[go];
            *(float4*)&Vs[r * 72 + c] = *(const float4*)&Vg[go];
        }
        if (tid < 64) Ms[tid] = mg[kt * 64 + tid];
        __syncthreads();

        float s[8][4];
#pragma unroll
        for (int ni = 0; ni < 8; ni++)
#pragma unroll
            for (int r = 0; r < 4; r++) s[ni][r] = 0.f;

#pragma unroll
        for (int kg = 0; kg < 8; kg++) {
            const int k = kg * 8;
            uint32_t a0 = Qsu[qrow * 68 + k + tig];
            uint32_t a1 = Qsu[(qrow + 8) * 68 + k + tig];
            uint32_t a2 = Qsu[qrow * 68 + k + tig + 4];
            uint32_t a3 = Qsu[(qrow + 8) * 68 + k + tig + 4];
#pragma unroll
            for (int ni = 0; ni < 8; ni++) {
                uint32_t b0 = Ksu[(ni * 8 + gid) * 68 + k + tig];
                uint32_t b1 = Ksu[(ni * 8 + gid) * 68 + k + tig + 4];
                mma_tf32(s[ni][0], s[ni][1], s[ni][2], s[ni][3], a0, a1, a2, a3, b0, b1);
            }
        }

        float tm0 = -3.0e38f, tm1 = -3.0e38f;
#pragma unroll
        for (int ni = 0; ni < 8; ni++) {
            int c0 = ni * 8 + tig * 2;
            if (Ms[c0] == 0)     { s[ni][0] = NEGV; s[ni][2] = NEGV; }
            if (Ms[c0 + 1] == 0) { s[ni][1] = NEGV; s[ni][3] = NEGV; }
            tm0 = fmaxf(tm0, fmaxf(s[ni][0], s[ni][1]));
            tm1 = fmaxf(tm1, fmaxf(s[ni][2], s[ni][3]));
        }
        tm0 = fmaxf(tm0, __shfl_xor_sync(0xffffffffu, tm0, 1));
        tm0 = fmaxf(tm0, __shfl_xor_sync(0xffffffffu, tm0, 2));
        tm1 = fmaxf(tm1, __shfl_xor_sync(0xffffffffu, tm1, 1));
        tm1 = fmaxf(tm1, __shfl_xor_sync(0xffffffffu, tm1, 2));

        float mn0 = fmaxf(m0, tm0), mn1 = fmaxf(m1, tm1);
        float cr0 = __expf(m0 - mn0), cr1 = __expf(m1 - mn1);

        float sum0 = 0.f, sum1 = 0.f;
#pragma unroll
        for (int ni = 0; ni < 8; ni++) {
            float p0 = __expf(s[ni][0] - mn0);
            float p1 = __expf(s[ni][1] - mn0);
            float p2 = __expf(s[ni][2] - mn1);
            float p3 = __expf(s[ni][3] - mn1);
            sum0 += p0 + p1; sum1 += p2 + p3;
            float2 lo, hi;
            lo.x = rtf(p0); lo.y = rtf(p1);
            hi.x = rtf(p2); hi.y = rtf(p3);
            *(float2*)&Ps[qrow * 68 + ni * 8 + tig * 2] = lo;
            *(float2*)&Ps[(qrow + 8) * 68 + ni * 8 + tig * 2] = hi;
        }
        sum0 += __shfl_xor_sync(0xffffffffu, sum0, 1);
        sum0 += __shfl_xor_sync(0xffffffffu, sum0, 2);
        sum1 += __shfl_xor_sync(0xffffffffu, sum1, 1);
        sum1 += __shfl_xor_sync(0xffffffffu, sum1, 2);

        l0 = l0 * cr0 + sum0;
        l1 = l1 * cr1 + sum1;
        m0 = mn0; m1 = mn1;

#pragma unroll
        for (int ng = 0; ng < 8; ng++) {
            oacc[ng][0] *= cr0; oacc[ng][1] *= cr0;
            oacc[ng][2] *= cr1; oacc[ng][3] *= cr1;
        }
        __syncwarp();

#pragma unroll
        for (int kg = 0; kg < 8; kg++) {
            const int k = kg * 8;
            uint32_t a0 = Psu[qrow * 68 + k + tig];
            uint32_t a1 = Psu[(qrow + 8) * 68 + k + tig];
            uint32_t a2 = Psu[qrow * 68 + k + tig + 4];
            uint32_t a3 = Psu[(qrow + 8) * 68 + k + tig + 4];
#pragma unroll
            for (int ng = 0; ng < 8; ng++) {
                uint32_t b0 = Vsu[(k + tig) * 72 + ng * 8 + gid];
                uint32_t b1 = Vsu[(k + tig + 4) * 72 + ng * 8 + gid];
                mma_tf32(oacc[ng][0], oacc[ng][1], oacc[ng][2], oacc[ng][3],
                         a0, a1, a2, a3, b0, b1);
            }
        }
    }

    // ctx feeds only the w_o GEMM -> write tf32-rounded
    float inv0 = 1.0f / l0, inv1 = 1.0f / l1;
    float* Og = O + base + (long long)qt * 128 * D_MODEL;
#pragma unroll
    for (int ng = 0; ng < 8; ng++) {
        int c = ng * 8 + tig * 2;
        *(float2*)&Og[(long long)qrow * D_MODEL + c] =
            make_float2(rtf(oacc[ng][0] * inv0), rtf(oacc[ng][1] * inv0));
        *(float2*)&Og[(long long)(qrow + 8) * D_MODEL + c] =
            make_float2(rtf(oacc[ng][2] * inv1), rtf(oacc[ng][3] * inv1));
    }
}

// ---------------- LayerNorm (ddof=1, /(std+eps)); RND -> tf32 output ---------
template<int RND>
__global__ void __launch_bounds__(256)
ln_k(const float* __restrict__ in, float* __restrict__ out,
     const float* __restrict__ alpha, const float* __restrict__ beta)
{
    const long long row = blockIdx.x;
    const float* p = in + row * D_MODEL;
    float* o = out + row * D_MODEL;
    const int tid = threadIdx.x;

    float4 x4 = ((const float4*)p)[tid];
    float s  = x4.x + x4.y + x4.z + x4.w;
    float sq = x4.x*x4.x + x4.y*x4.y + x4.z*x4.z + x4.w*x4.w;

    __shared__ float rs[256], rq[256];
    rs[tid] = s; rq[tid] = sq; __syncthreads();
    for (int st = 128; st > 0; st >>= 1) {
        if (tid < st) { rs[tid] += rs[tid + st]; rq[tid] += rq[tid + st]; }
        __syncthreads();
    }
    float mean = rs[0] * (1.0f / D_MODEL);
    float var  = (rq[0] - rs[0] * mean) * (1.0f / (D_MODEL - 1));
    var = fmaxf(var, 0.f);
    float inv = 1.0f / (sqrtf(var) + LN_EPS);

    float4 a4 = ((const float4*)alpha)[tid];
    float4 b4 = ((const float4*)beta)[tid];
    float4 o4;
    o4.x = a4.x * (x4.x - mean) * inv + b4.x;
    o4.y = a4.y * (x4.y - mean) * inv + b4.y;
    o4.z = a4.z * (x4.z - mean) * inv + b4.z;
    o4.w = a4.w * (x4.w - mean) * inv + b4.w;
    if (RND) { o4.x = rtf(o4.x); o4.y = rtf(o4.y); o4.z = rtf(o4.z); o4.w = rtf(o4.w); }
    ((float4*)o)[tid] = o4;
}

// ---------------- launcher ---------------------------------------------------
extern "C" void kernel_launch(void* const* d_in, const int* in_sizes, int n_in,
                              void* d_out, int out_size)
{
    const float* x     = (const float*)d_in[0];
    const int*   mask  = (const int*)  d_in[1];
    const float* w_q   = (const float*)d_in[2];
    const float* w_k   = (const float*)d_in[3];
    const float* w_v   = (const float*)d_in[4];
    const float* w_o   = (const float*)d_in[5];
    const float* W1    = (const float*)d_in[6];
    const float* b1    = (const float*)d_in[7];
    const float* W2    = (const float*)d_in[8];
    const float* b2    = (const float*)d_in[9];
    const float* al1   = (const float*)d_in[10];
    const float* be1   = (const float*)d_in[11];
    const float* al2   = (const float*)d_in[12];
    const float* be2   = (const float*)d_in[13];
    float* out = (float*)d_out;

    float *Q, *Kb, *V, *CTX, *T1, *X1, *H, *T2;
    float *XR, *WQ, *WK, *WV, *WO, *W1R, *W2R;
    cudaGetSymbolAddress((void**)&Q,   g_Q);
    cudaGetSymbolAddress((void**)&Kb,  g_Kb);
    cudaGetSymbolAddress((void**)&V,   g_V);
    cudaGetSymbolAddress((void**)&CTX, g_ctx);
    cudaGetSymbolAddress((void**)&T1,  g_t1);
    cudaGetSymbolAddress((void**)&X1,  g_x1);
    cudaGetSymbolAddress((void**)&H,   g_h);
    cudaGetSymbolAddress((void**)&T2,  g_t2);
    cudaGetSymbolAddress((void**)&XR,  g_xr);
    cudaGetSymbolAddress((void**)&WQ,  g_wqr);
    cudaGetSymbolAddress((void**)&WK,  g_wkr);
    cudaGetSymbolAddress((void**)&WV,  g_wvr);
    cudaGetSymbolAddress((void**)&WO,  g_wor);
    cudaGetSymbolAddress((void**)&W1R, g_W1r);
    cudaGetSymbolAddress((void**)&W2R, g_W2r);

    cudaFuncSetAttribute(fa_k, cudaFuncAttributeMaxDynamicSharedMemorySize, FA_SMEM);
    cudaFuncSetAttribute(tgemm_k<EPI_TF32>, cudaFuncAttributeMaxDynamicSharedMemorySize, GEMM_SMEM);
    cudaFuncSetAttribute(tgemm_k<EPI_RESID>, cudaFuncAttributeMaxDynamicSharedMemorySize, GEMM_SMEM);
    cudaFuncSetAttribute(tgemm_k<EPI_BIAS|EPI_RELU|EPI_TF32>, cudaFuncAttributeMaxDynamicSharedMemorySize, GEMM_SMEM);
    cudaFuncSetAttribute(tgemm_k<EPI_BIAS|EPI_RESID>, cudaFuncAttributeMaxDynamicSharedMemorySize, GEMM_SMEM);

    const dim3 blk(256);
    auto grd = [](int N, int M) {
        return dim3((unsigned)(N / 128), (unsigned)(M / 128), 1);
    };

    // 0: pre-round operands to tf32
    const int MM = 1024 * 1024;
    rnd_k<<<(NTOK * D_MODEL / 4 + 255) / 256, blk>>>(x,   XR,  NTOK * D_MODEL / 4);
    rnd_k<<<(MM / 4 + 255) / 256, blk>>>(w_q, WQ,  MM / 4);
    rnd_k<<<(MM / 4 + 255) / 256, blk>>>(w_k, WK,  MM / 4);
    rnd_k<<<(MM / 4 + 255) / 256, blk>>>(w_v, WV,  MM / 4);
    rnd_k<<<(MM / 4 + 255) / 256, blk>>>(w_o, WO,  MM / 4);
    rnd_k<<<(4 * MM / 4 + 255) / 256, blk>>>(W1, W1R, 4 * MM / 4);
    rnd_k<<<(4 * MM / 4 + 255) / 256, blk>>>(W2, W2R, 4 * MM / 4);

    // 1-3: Q/K/V projections (Q pre-scaled by 0.125; outputs tf32 for fa_k)
    tgemm_k<EPI_TF32><<<grd(D_MODEL, NTOK), blk, GEMM_SMEM>>>(XR, WQ, Q, D_MODEL, D_MODEL,
        D_MODEL, D_MODEL, D_MODEL, 0.125f, nullptr, nullptr);
    tgemm_k<EPI_TF32><<<grd(D_MODEL, NTOK), blk, GEMM_SMEM>>>(XR, WK, Kb, D_MODEL, D_MODEL,
        D_MODEL, D_MODEL, D_MODEL, 1.f, nullptr, nullptr);
    tgemm_k<EPI_TF32><<<grd(D_MODEL, NTOK), blk, GEMM_SMEM>>>(XR, WV, V, D_MODEL, D_MODEL,
        D_MODEL, D_MODEL, D_MODEL, 1.f, nullptr, nullptr);

    // 4: fused attention -> ctx (tf32-rounded)
    fa_k<<<dim3(SS / 128, BB * HEADS), blk, FA_SMEM>>>(Q, Kb, V, mask, CTX);

    // 5: t1 = ctx @ w_o + x
    tgemm_k<EPI_RESID><<<grd(D_MODEL, NTOK), blk, GEMM_SMEM>>>(CTX, WO, T1, D_MODEL, D_MODEL,
        D_MODEL, D_MODEL, D_MODEL, 1.f, nullptr, x);

    // 6: x1 = LN1(t1), tf32-rounded (feeds GEMM 7 A and GEMM 8 resid)
    ln_k<1><<<NTOK, blk>>>(T1, X1, al1, be1);

    // 7: h = relu(x1 @ W1 + b1), tf32-rounded
    tgemm_k<EPI_BIAS|EPI_RELU|EPI_TF32><<<grd(D_FF, NTOK), blk, GEMM_SMEM>>>(X1, W1R, H, D_FF, D_MODEL,
        D_MODEL, D_FF, D_FF, 1.f, b1, nullptr);

    // 8: t2 = h @ W2 + b2 + x1
    tgemm_k<EPI_BIAS|EPI_RESID><<<grd(D_MODEL, NTOK), blk, GEMM_SMEM>>>(H, W2R, T2, D_MODEL, D_FF,
        D_FF, D_MODEL, D_MODEL, 1.f, b2, X1);

    // 9: out = LN2(t2), full fp32
    ln_k<0><<<NTOK, blk>>>(T2, out, al2, be2);
}

// round 8
// speedup vs baseline: 2.4956x; 1.4053x over previous
#include <cuda_runtime.h>
#include <cuda_bf16.h>
#include <cuda_fp16.h>
#include <cstdint>

#define D_MODEL 1024
#define HEADS   16
#define DK      64
#define D_FF    4096
#define BB      2
#define SS      2048
#define NTOK    (BB * SS)        // 4096
#define LN_EPS  1e-6f
#define NEGV    (-1e9f)

// ---------------- scratch (device globals; no runtime allocation) -----------
__device__ float  g_Q  [NTOK * D_MODEL];
__device__ float  g_Kb [NTOK * D_MODEL];
__device__ float  g_V  [NTOK * D_MODEL];
__device__ __half g_ctx[NTOK * D_MODEL];
__device__ float  g_t1 [NTOK * D_MODEL];
__device__ __half g_x1h[NTOK * D_MODEL];
__device__ float  g_x1f[NTOK * D_MODEL];
__device__ __half g_h  [NTOK * D_FF];
__device__ float  g_t2 [NTOK * D_MODEL];
// fp16 operand copies (weights transposed to [N][K])
__device__ __half g_xr [NTOK * D_MODEL];
__device__ __half g_wqt[D_MODEL * D_MODEL];
__device__ __half g_wkt[D_MODEL * D_MODEL];
__device__ __half g_wvt[D_MODEL * D_MODEL];
__device__ __half g_wot[D_MODEL * D_MODEL];
__device__ __half g_W1t[D_FF * D_MODEL];   // [4096][1024]
__device__ __half g_W2t[D_MODEL * D_FF];   // [1024][4096]

#define EPI_BIAS    1
#define EPI_RELU    2
#define EPI_RESID   4
#define EPI_TF32    8
#define EPI_HALFOUT 16

__device__ __forceinline__ uint32_t f2tf32(float x) {
    uint32_t y;
    asm("cvt.rna.tf32.f32 %0, %1;" : "=r"(y) : "f"(x));
    return y;
}
__device__ __forceinline__ float rtf(float x) { return __uint_as_float(f2tf32(x)); }

__device__ __forceinline__ void mma_tf32(float& c0, float& c1, float& c2, float& c3,
                                         uint32_t a0, uint32_t a1, uint32_t a2, uint32_t a3,
                                         uint32_t b0, uint32_t b1) {
    asm volatile(
        "mma.sync.aligned.m16n8k8.row.col.f32.tf32.tf32.f32 "
        "{%0,%1,%2,%3}, {%4,%5,%6,%7}, {%8,%9}, {%0,%1,%2,%3};"
        : "+f"(c0), "+f"(c1), "+f"(c2), "+f"(c3)
        : "r"(a0), "r"(a1), "r"(a2), "r"(a3), "r"(b0), "r"(b1));
}

__device__ __forceinline__ void mma_f16(float& c0, float& c1, float& c2, float& c3,
                                        uint32_t a0, uint32_t a1, uint32_t a2, uint32_t a3,
                                        uint32_t b0, uint32_t b1) {
    asm volatile(
        "mma.sync.aligned.m16n8k16.row.col.f32.f16.f16.f32 "
        "{%0,%1,%2,%3}, {%4,%5,%6,%7}, {%8,%9}, {%0,%1,%2,%3};"
        : "+f"(c0), "+f"(c1), "+f"(c2), "+f"(c3)
        : "r"(a0), "r"(a1), "r"(a2), "r"(a3), "r"(b0), "r"(b1));
}

__device__ __forceinline__ void cp16(uint32_t saddr, const void* gaddr) {
    asm volatile("cp.async.cg.shared.global [%0], [%1], 16;" :: "r"(saddr), "l"(gaddr));
}
__device__ __forceinline__ void cp_commit() {
    asm volatile("cp.async.commit_group;");
}
template<int N> __device__ __forceinline__ void cp_wait() {
    asm volatile("cp.async.wait_group %0;" :: "n"(N));
}

// ---------------- prep: fp32 -> fp16 elementwise (x -> xr) -------------------
__global__ void __launch_bounds__(256)
f2h_k(const float* __restrict__ in, __half* __restrict__ out, int n4)
{
    int i = blockIdx.x * 256 + threadIdx.x;
    if (i >= n4) return;
    float4 v = ((const float4*)in)[i];
    ((__half2*)out)[2*i]     = __floats2half2_rn(v.x, v.y);
    ((__half2*)out)[2*i + 1] = __floats2half2_rn(v.z, v.w);
}

// ---------------- prep: transpose + convert weight W[K][N] -> WT[N][K] fp16 --
__global__ void __launch_bounds__(256)
wt_k(const float* __restrict__ W, __half* __restrict__ WT, int K, int N)
{
    __shared__ float t[32][33];
    const int tx = threadIdx.x & 31, ty = threadIdx.x >> 5;   // 32 x 8
    const int n0 = blockIdx.x * 32, k0 = blockIdx.y * 32;
#pragma unroll
    for (int j = 0; j < 4; j++)
        t[ty + j * 8][tx] = W[(long long)(k0 + ty + j * 8) * N + n0 + tx];
    __syncthreads();
#pragma unroll
    for (int j = 0; j < 4; j++)
        WT[(long long)(n0 + ty + j * 8) * K + k0 + tx] = __float2half(t[tx][ty + j * 8]);
}

// ---------------- fp16 tensor-core GEMM, 3-stage cp.async pipeline -----------
// C[m,n] = scale * sum_k A[m,k] * BT[n,k]   (A fp16 [M][K], BT fp16 [N][K])
// Block tile 128x128x64, 8 warps of 64x32, m16n8k16 f16 MMA, fp32 accumulate.
// M,N multiples of 128; K multiple of 128.
#define HSTR 72                 // halves per smem row (64 + 8 pad) = 36 words
#define HTSZ (128 * HSTR)       // halves per tile (A or B)
#define HSTG (2 * HTSZ)         // halves per stage
#define GEMM_SMEM (3 * HSTG * 2)

template<int EPI>
__global__ void __launch_bounds__(256, 2)
tgemm_h(const __half* __restrict__ A, const __half* __restrict__ BT,
        void* __restrict__ Cv, int N, int K,
        int lda, int ldb, int ldc,
        float scale, const float* __restrict__ bias,
        const float* __restrict__ resid)
{
    extern __shared__ __half hsm[];
    const int tid  = threadIdx.x;
    const int lane = tid & 31;
    const int wid  = tid >> 5;
    const int wm   = wid >> 2;
    const int wn   = wid & 3;
    const int gid  = lane >> 2;
    const int tig  = lane & 3;

    const int row0 = blockIdx.y * 128;
    const int col0 = blockIdx.x * 128;

    int rw[4], sg[4];
#pragma unroll
    for (int i = 0; i < 4; i++) {
        int f = tid + i * 256;      // 0..1023
        rw[i] = f >> 3;             // row 0..127
        sg[i] = (f & 7) * 8;        // half offset 0..56 (16B chunks)
    }

    const uint32_t smb = (uint32_t)__cvta_generic_to_shared(hsm);
    const int nkt = K >> 6;         // K / 64

    auto issue = [&](int kt) {
        const int buf = kt % 3;
        const uint32_t as = smb + (uint32_t)(buf * HSTG) * 2u;
        const uint32_t bs = as + (uint32_t)HTSZ * 2u;
        const int k0 = kt * 64;
#pragma unroll
        for (int i = 0; i < 4; i++) {
            cp16(as + (uint32_t)(rw[i] * HSTR + sg[i]) * 2u,
                 &A[(long long)(row0 + rw[i]) * lda + k0 + sg[i]]);
            cp16(bs + (uint32_t)(rw[i] * HSTR + sg[i]) * 2u,
                 &BT[(long long)(col0 + rw[i]) * ldb + k0 + sg[i]]);
        }
        cp_commit();
    };

    issue(0); issue(1);

    float acc[4][4][4];
#pragma unroll
    for (int mi = 0; mi < 4; mi++)
#pragma unroll
        for (int ni = 0; ni < 4; ni++)
#pragma unroll
            for (int r = 0; r < 4; r++) acc[mi][ni][r] = 0.f;

    for (int kt = 0; kt < nkt; kt++) {
        if (kt + 1 < nkt) cp_wait<1>();
        else              cp_wait<0>();   // tail: drain the last pending group
        __syncthreads();

        const uint32_t* Asu = (const uint32_t*)(hsm + (kt % 3) * HSTG);
        const uint32_t* Bsu = Asu + HTSZ / 2;   // word index
#pragma unroll
        for (int kg = 0; kg < 4; kg++) {
            const int kw = kg * 8;              // word offset (= 16 halves of k)
            uint32_t af[4][4], bf[4][2];
#pragma unroll
            for (int mi = 0; mi < 4; mi++) {
                int m = wm * 64 + mi * 16 + gid;
                af[mi][0] = Asu[m * 36 + kw + tig];
                af[mi][1] = Asu[(m + 8) * 36 + kw + tig];
                af[mi][2] = Asu[m * 36 + kw + tig + 4];
                af[mi][3] = Asu[(m + 8) * 36 + kw + tig + 4];
            }
#pragma unroll
            for (int ni = 0; ni < 4; ni++) {
                int n = wn * 32 + ni * 8 + gid;
                bf[ni][0] = Bsu[n * 36 + kw + tig];
                bf[ni][1] = Bsu[n * 36 + kw + tig + 4];
            }
#pragma unroll
            for (int mi = 0; mi < 4; mi++)
#pragma unroll
                for (int ni = 0; ni < 4; ni++)
                    mma_f16(acc[mi][ni][0], acc[mi][ni][1], acc[mi][ni][2], acc[mi][ni][3],
                            af[mi][0], af[mi][1], af[mi][2], af[mi][3],
                            bf[ni][0], bf[ni][1]);
        }
        if (kt + 2 < nkt) issue(kt + 2);
    }

    // ---- epilogue ----
#pragma unroll
    for (int mi = 0; mi < 4; mi++) {
#pragma unroll
        for (int ni = 0; ni < 4; ni++) {
            int r0 = row0 + wm * 64 + mi * 16 + gid;
            int cb = col0 + wn * 32 + ni * 8 + tig * 2;
#pragma unroll
            for (int half_ = 0; half_ < 2; half_++) {
                int rr = r0 + half_ * 8;
                float v0 = acc[mi][ni][half_ * 2 + 0] * scale;
                float v1 = acc[mi][ni][half_ * 2 + 1] * scale;
                if (EPI & EPI_BIAS)  { v0 += bias[cb]; v1 += bias[cb + 1]; }
                if (EPI & EPI_RESID) {
                    const float2 rv = *(const float2*)&resid[(long long)rr * ldc + cb];
                    v0 += rv.x; v1 += rv.y;
                }
                if (EPI & EPI_RELU)  { v0 = fmaxf(v0, 0.f); v1 = fmaxf(v1, 0.f); }
                if (EPI & EPI_HALFOUT) {
                    *(__half2*)&((__half*)Cv)[(long long)rr * ldc + cb] = __floats2half2_rn(v0, v1);
                } else {
                    if (EPI & EPI_TF32) { v0 = rtf(v0); v1 = rtf(v1); }
                    *(float2*)&((float*)Cv)[(long long)rr * ldc + cb] = make_float2(v0, v1);
                }
            }
        }
    }
}

// ---------------- fused flash attention (tf32, fp32 Q/K/V, fp16 ctx out) -----
#define FA_SMEM ((128*68 + 64*68 + 64*72 + 128*68) * 4 + 256)

__global__ void __launch_bounds__(256, 2)
fa_k(const float* __restrict__ Q, const float* __restrict__ K,
     const float* __restrict__ V, const int* __restrict__ mask,
     __half* __restrict__ O)
{
    extern __shared__ float sm[];
    float* Qs = sm;
    float* Ks = Qs + 128 * 68;
    float* Vs = Ks + 64 * 68;
    float* Ps = Vs + 64 * 72;
    int*   Ms = (int*)(Ps + 128 * 68);

    const int qt  = blockIdx.x;
    const int z   = blockIdx.y;
    const int b   = z >> 4, h = z & 15;
    const int tid = threadIdx.x, lane = tid & 31, w = tid >> 5;
    const int gid = lane >> 2, tig = lane & 3;

    const long long base = ((long long)b * SS) * D_MODEL + h * DK;
    const float* Qg = Q + base + (long long)qt * 128 * D_MODEL;
    const float* Kg = K + base;
    const float* Vg = V + base;
    const int*   mg = mask + (long long)b * SS;

#pragma unroll
    for (int i = 0; i < 8; i++) {
        int idx = tid + i * 256;
        int r = idx >> 4, c = (idx & 15) * 4;
        *(float4*)&Qs[r * 68 + c] = *(const float4*)&Qg[(long long)r * D_MODEL + c];
    }

    float m0 = -INFINITY, m1 = -INFINITY;
    float l0 = 0.f, l1 = 0.f;
    float oacc[8][4];
#pragma unroll
    for (int ng = 0; ng < 8; ng++)
#pragma unroll
        for (int r = 0; r < 4; r++) oacc[ng][r] = 0.f;

    const uint32_t* Qsu = (const uint32_t*)Qs;
    const uint32_t* Ksu = (const uint32_t*)Ks;
    const uint32_t* Vsu = (const uint32_t*)Vs;
    const uint32_t* Psu = (const uint32_t*)Ps;
    const int qrow = w * 16 + gid;

    for (int kt = 0; kt < SS / 64; kt++) {
        __syncthreads();
#pragma unroll
        for (int i = 0; i < 4; i++) {
            int idx = tid + i * 256;
            int r = idx >> 4, c = (idx & 15) * 4;
            long long go = (long long)(kt * 64 + r) * D_MODEL + c;
            *(float4*)&Ks[r * 68 + c] = *(const float4*)&Kg[go];
            *(float4*)&Vs[r * 72 + c] = *(const float4*)&Vg[go];
        }
        if (tid < 64) Ms[tid] = mg[kt * 64 + tid];
        __syncthreads();

        float s[8][4];
#pragma unroll
        for (int ni = 0; ni < 8; ni++)
#pragma unroll
            for (int r = 0; r < 4; r++) s[ni][r] = 0.f;

#pragma unroll
        for (int kg = 0; kg < 8; kg++) {
            const int k = kg * 8;
            uint32_t a0 = Qsu[qrow * 68 + k + tig];
            uint32_t a1 = Qsu[(qrow + 8) * 68 + k + tig];
            uint32_t a2 = Qsu[qrow * 68 + k + tig + 4];
            uint32_t a3 = Qsu[(qrow + 8) * 68 + k + tig + 4];
#pragma unroll
            for (int ni = 0; ni < 8; ni++) {
                uint32_t b0 = Ksu[(ni * 8 + gid) * 68 + k + tig];
                uint32_t b1 = Ksu[(ni * 8 + gid) * 68 + k + tig + 4];
                mma_tf32(s[ni][0], s[ni][1], s[ni][2], s[ni][3], a0, a1, a2, a3, b0, b1);
            }
        }

        float tm0 = -3.0e38f, tm1 = -3.0e38f;
#pragma unroll
        for (int ni = 0; ni < 8; ni++) {
            int c0 = ni * 8 + tig * 2;
            if (Ms[c0] == 0)     { s[ni][0] = NEGV; s[ni][2] = NEGV; }
            if (Ms[c0 + 1] == 0) { s[ni][1] = NEGV; s[ni][3] = NEGV; }
            tm0 = fmaxf(tm0, fmaxf(s[ni][0], s[ni][1]));
            tm1 = fmaxf(tm1, fmaxf(s[ni][2], s[ni][3]));
        }
        tm0 = fmaxf(tm0, __shfl_xor_sync(0xffffffffu, tm0, 1));
        tm0 = fmaxf(tm0, __shfl_xor_sync(0xffffffffu, tm0, 2));
        tm1 = fmaxf(tm1, __shfl_xor_sync(0xffffffffu, tm1, 1));
        tm1 = fmaxf(tm1, __shfl_xor_sync(0xffffffffu, tm1, 2));

        float mn0 = fmaxf(m0, tm0), mn1 = fmaxf(m1, tm1);
        float cr0 = __expf(m0 - mn0), cr1 = __expf(m1 - mn1);

        float sum0 = 0.f, sum1 = 0.f;
#pragma unroll
        for (int ni = 0; ni < 8; ni++) {
            float p0 = __expf(s[ni][0] - mn0);
            float p1 = __expf(s[ni][1] - mn0);
            float p2 = __expf(s[ni][2] - mn1);
            float p3 = __expf(s[ni][3] - mn1);
            sum0 += p0 + p1; sum1 += p2 + p3;
            float2 lo, hi;
            lo.x = rtf(p0); lo.y = rtf(p1);
            hi.x = rtf(p2); hi.y = rtf(p3);
            *(float2*)&Ps[qrow * 68 + ni * 8 + tig * 2] = lo;
            *(float2*)&Ps[(qrow + 8) * 68 + ni * 8 + tig * 2] = hi;
        }
        sum0 += __shfl_xor_sync(0xffffffffu, sum0, 1);
        sum0 += __shfl_xor_sync(0xffffffffu, sum0, 2);
        sum1 += __shfl_xor_sync(0xffffffffu, sum1, 1);
        sum1 += __shfl_xor_sync(0xffffffffu, sum1, 2);

        l0 = l0 * cr0 + sum0;
        l1 = l1 * cr1 + sum1;
        m0 = mn0; m1 = mn1;

#pragma unroll
        for (int ng = 0; ng < 8; ng++) {
            oacc[ng][0] *= cr0; oacc[ng][1] *= cr0;
            oacc[ng][2] *= cr1; oacc[ng][3] *= cr1;
        }
        __syncwarp();

#pragma unroll
        for (int kg = 0; kg < 8; kg++) {
            const int k = kg * 8;
            uint32_t a0 = Psu[qrow * 68 + k + tig];
            uint32_t a1 = Psu[(qrow + 8) * 68 + k + tig];
            uint32_t a2 = Psu[qrow * 68 + k + tig + 4];
            uint32_t a3 = Psu[(qrow + 8) * 68 + k + tig + 4];
#pragma unroll
            for (int ng = 0; ng < 8; ng++) {
                uint32_t b0 = Vsu[(k + tig) * 72 + ng * 8 + gid];
                uint32_t b1 = Vsu[(k + tig + 4) * 72 + ng * 8 + gid];
                mma_tf32(oacc[ng][0], oacc[ng][1], oacc[ng][2], oacc[ng][3],
                         a0, a1, a2, a3, b0, b1);
            }
        }
    }

    float inv0 = 1.0f / l0, inv1 = 1.0f / l1;
    __half* Og = O + base + (long long)qt * 128 * D_MODEL;
#pragma unroll
    for (int ng = 0; ng < 8; ng++) {
        int c = ng * 8 + tig * 2;
        *(__half2*)&Og[(long long)qrow * D_MODEL + c] =
            __floats2half2_rn(oacc[ng][0] * inv0, oacc[ng][1] * inv0);
        *(__half2*)&Og[(long long)(qrow + 8) * D_MODEL + c] =
            __floats2half2_rn(oacc[ng][2] * inv1, oacc[ng][3] * inv1);
    }
}

// ---------------- LayerNorm (ddof=1, /(std+eps)) -----------------------------
// WH: also emit fp16 copy (GEMM operand)
template<int WH>
__global__ void __launch_bounds__(256)
ln_k(const float* __restrict__ in, float* __restrict__ out,
     __half* __restrict__ outh,
     const float* __restrict__ alpha, const float* __restrict__ beta)
{
    const long long row = blockIdx.x;
    const float* p = in + row * D_MODEL;
    const int tid = threadIdx.x;

    float4 x4 = ((const float4*)p)[tid];
    float s  = x4.x + x4.y + x4.z + x4.w;
    float sq = x4.x*x4.x + x4.y*x4.y + x4.z*x4.z + x4.w*x4.w;

    __shared__ float rs[256], rq[256];
    rs[tid] = s; rq[tid] = sq; __syncthreads();
    for (int st = 128; st > 0; st >>= 1) {
        if (tid < st) { rs[tid] += rs[tid + st]; rq[tid] += rq[tid + st]; }
        __syncthreads();
    }
    float mean = rs[0] * (1.0f / D_MODEL);
    float var  = (rq[0] - rs[0] * mean) * (1.0f / (D_MODEL - 1));
    var = fmaxf(var, 0.f);
    float inv = 1.0f / (sqrtf(var) + LN_EPS);

    float4 a4 = ((const float4*)alpha)[tid];
    float4 b4 = ((const float4*)beta)[tid];
    float4 o4;
    o4.x = a4.x * (x4.x - mean) * inv + b4.x;
    o4.y = a4.y * (x4.y - mean) * inv + b4.y;
    o4.z = a4.z * (x4.z - mean) * inv + b4.z;
    o4.w = a4.w * (x4.w - mean) * inv + b4.w;
    ((float4*)(out + row * D_MODEL))[tid] = o4;
    if (WH) {
        __half2* oh = (__half2*)(outh + row * D_MODEL);
        oh[tid * 2]     = __floats2half2_rn(o4.x, o4.y);
        oh[tid * 2 + 1] = __floats2half2_rn(o4.z, o4.w);
    }
}

// ---------------- launcher ---------------------------------------------------
extern "C" void kernel_launch(void* const* d_in, const int* in_sizes, int n_in,
                              void* d_out, int out_size)
{
    const float* x     = (const float*)d_in[0];
    const int*   mask  = (const int*)  d_in[1];
    const float* w_q   = (const float*)d_in[2];
    const float* w_k   = (const float*)d_in[3];
    const float* w_v   = (const float*)d_in[4];
    const float* w_o   = (const float*)d_in[5];
    const float* W1    = (const float*)d_in[6];
    const float* b1    = (const float*)d_in[7];
    const float* W2    = (const float*)d_in[8];
    const float* b2    = (const float*)d_in[9];
    const float* al1   = (const float*)d_in[10];
    const float* be1   = (const float*)d_in[11];
    const float* al2   = (const float*)d_in[12];
    const float* be2   = (const float*)d_in[13];
    float* out = (float*)d_out;

    float *Q, *Kb, *V, *T1, *X1F, *T2;
    __half *CTX, *X1H, *H, *XR, *WQT, *WKT, *WVT, *WOT, *W1T, *W2T;
    cudaGetSymbolAddress((void**)&Q,   g_Q);
    cudaGetSymbolAddress((void**)&Kb,  g_Kb);
    cudaGetSymbolAddress((void**)&V,   g_V);
    cudaGetSymbolAddress((void**)&CTX, g_ctx);
    cudaGetSymbolAddress((void**)&T1,  g_t1);
    cudaGetSymbolAddress((void**)&X1H, g_x1h);
    cudaGetSymbolAddress((void**)&X1F, g_x1f);
    cudaGetSymbolAddress((void**)&H,   g_h);
    cudaGetSymbolAddress((void**)&T2,  g_t2);
    cudaGetSymbolAddress((void**)&XR,  g_xr);
    cudaGetSymbolAddress((void**)&WQT, g_wqt);
    cudaGetSymbolAddress((void**)&WKT, g_wkt);
    cudaGetSymbolAddress((void**)&WVT, g_wvt);
    cudaGetSymbolAddress((void**)&WOT, g_wot);
    cudaGetSymbolAddress((void**)&W1T, g_W1t);
    cudaGetSymbolAddress((void**)&W2T, g_W2t);

    cudaFuncSetAttribute(fa_k, cudaFuncAttributeMaxDynamicSharedMemorySize, FA_SMEM);
    cudaFuncSetAttribute(tgemm_h<EPI_TF32>, cudaFuncAttributeMaxDynamicSharedMemorySize, GEMM_SMEM);
    cudaFuncSetAttribute(tgemm_h<EPI_RESID>, cudaFuncAttributeMaxDynamicSharedMemorySize, GEMM_SMEM);
    cudaFuncSetAttribute(tgemm_h<EPI_BIAS|EPI_RELU|EPI_HALFOUT>, cudaFuncAttributeMaxDynamicSharedMemorySize, GEMM_SMEM);
    cudaFuncSetAttribute(tgemm_h<EPI_BIAS|EPI_RESID>, cudaFuncAttributeMaxDynamicSharedMemorySize, GEMM_SMEM);

    const dim3 blk(256);
    auto grd = [](int N, int M) {
        return dim3((unsigned)(N / 128), (unsigned)(M / 128), 1);
    };

    // 0: operand prep — x to fp16; weights transposed+fp16
    f2h_k<<<(NTOK * D_MODEL / 4 + 255) / 256, blk>>>(x, XR, NTOK * D_MODEL / 4);
    wt_k<<<dim3(32, 32), blk>>>(w_q, WQT, D_MODEL, D_MODEL);
    wt_k<<<dim3(32, 32), blk>>>(w_k, WKT, D_MODEL, D_MODEL);
    wt_k<<<dim3(32, 32), blk>>>(w_v, WVT, D_MODEL, D_MODEL);
    wt_k<<<dim3(32, 32), blk>>>(w_o, WOT, D_MODEL, D_MODEL);
    wt_k<<<dim3(128, 32), blk>>>(W1, W1T, D_MODEL, D_FF);   // [1024][4096] -> [4096][1024]
    wt_k<<<dim3(32, 128), blk>>>(W2, W2T, D_FF, D_MODEL);   // [4096][1024] -> [1024][4096]

    // 1-3: Q/K/V projections (fp16 in, fp32/tf32-rounded out; Q pre-scaled)
    tgemm_h<EPI_TF32><<<grd(D_MODEL, NTOK), blk, GEMM_SMEM>>>(XR, WQT, Q, D_MODEL, D_MODEL,
        D_MODEL, D_MODEL, D_MODEL, 0.125f, nullptr, nullptr);
    tgemm_h<EPI_TF32><<<grd(D_MODEL, NTOK), blk, GEMM_SMEM>>>(XR, WKT, Kb, D_MODEL, D_MODEL,
        D_MODEL, D_MODEL, D_MODEL, 1.f, nullptr, nullptr);
    tgemm_h<EPI_TF32><<<grd(D_MODEL, NTOK), blk, GEMM_SMEM>>>(XR, WVT, V, D_MODEL, D_MODEL,
        D_MODEL, D_MODEL, D_MODEL, 1.f, nullptr, nullptr);

    // 4: fused attention -> ctx (fp16)
    fa_k<<<dim3(SS / 128, BB * HEADS), blk, FA_SMEM>>>(Q, Kb, V, mask, CTX);

    // 5: t1 = ctx @ w_o + x  (fp32 out)
    tgemm_h<EPI_RESID><<<grd(D_MODEL, NTOK), blk, GEMM_SMEM>>>(CTX, WOT, T1, D_MODEL, D_MODEL,
        D_MODEL, D_MODEL, D_MODEL, 1.f, nullptr, x);

    // 6: x1 = LN1(t1) -> fp32 (residual) + fp16 (GEMM operand)
    ln_k<1><<<NTOK, blk>>>(T1, X1F, X1H, al1, be1);

    // 7: h = relu(x1 @ W1 + b1) -> fp16
    tgemm_h<EPI_BIAS|EPI_RELU|EPI_HALFOUT><<<grd(D_FF, NTOK), blk, GEMM_SMEM>>>(X1H, W1T, H,
        D_FF, D_MODEL, D_MODEL, D_MODEL, D_FF, 1.f, b1, nullptr);

    // 8: t2 = h @ W2 + b2 + x1  (fp32 out)
    tgemm_h<EPI_BIAS|EPI_RESID><<<grd(D_MODEL, NTOK), blk, GEMM_SMEM>>>(H, W2T, T2,
        D_MODEL, D_FF, D_FF, D_FF, D_MODEL, 1.f, b2, X1F);

    // 9: out = LN2(t2), full fp32
    ln_k<0><<<NTOK, blk>>>(T2, out, nullptr, al2, be2);
}

// round 11
// speedup vs baseline: 2.8152x; 1.1280x over previous
#include <cuda_runtime.h>
#include <cuda_bf16.h>
#include <cuda_fp16.h>
#include <cstdint>

#define D_MODEL 1024
#define HEADS   16
#define DK      64
#define D_FF    4096
#define BB      2
#define SS      2048
#define NTOK    (BB * SS)        // 4096
#define LN_EPS  1e-6f
#define NEGV    (-1e9f)

// ---------------- scratch (device globals; no runtime allocation) -----------
__device__ __half g_Q  [NTOK * D_MODEL];
__device__ __half g_Kb [NTOK * D_MODEL];
__device__ __half g_V  [NTOK * D_MODEL];
__device__ __half g_ctx[NTOK * D_MODEL];
__device__ float  g_t1 [NTOK * D_MODEL];
__device__ __half g_x1h[NTOK * D_MODEL];
__device__ float  g_x1f[NTOK * D_MODEL];
__device__ __half g_h  [NTOK * D_FF];
__device__ float  g_t2 [NTOK * D_MODEL];
// fp16 operand copies (weights transposed to [N][K])
__device__ __half g_xr [NTOK * D_MODEL];
__device__ __half g_wqt[D_MODEL * D_MODEL];
__device__ __half g_wkt[D_MODEL * D_MODEL];
__device__ __half g_wvt[D_MODEL * D_MODEL];
__device__ __half g_wot[D_MODEL * D_MODEL];
__device__ __half g_W1t[D_FF * D_MODEL];   // [4096][1024]
__device__ __half g_W2t[D_MODEL * D_FF];   // [1024][4096]

#define EPI_BIAS    1
#define EPI_RELU    2
#define EPI_RESID   4
#define EPI_HALFOUT 16

__device__ __forceinline__ void mma_f16(float& c0, float& c1, float& c2, float& c3,
                                        uint32_t a0, uint32_t a1, uint32_t a2, uint32_t a3,
                                        uint32_t b0, uint32_t b1) {
    asm volatile(
        "mma.sync.aligned.m16n8k16.row.col.f32.f16.f16.f32 "
        "{%0,%1,%2,%3}, {%4,%5,%6,%7}, {%8,%9}, {%0,%1,%2,%3};"
        : "+f"(c0), "+f"(c1), "+f"(c2), "+f"(c3)
        : "r"(a0), "r"(a1), "r"(a2), "r"(a3), "r"(b0), "r"(b1));
}

__device__ __forceinline__ void cp16(uint32_t saddr, const void* gaddr) {
    asm volatile("cp.async.cg.shared.global [%0], [%1], 16;" :: "r"(saddr), "l"(gaddr));
}
__device__ __forceinline__ void cp_commit() {
    asm volatile("cp.async.commit_group;");
}
template<int N> __device__ __forceinline__ void cp_wait() {
    asm volatile("cp.async.wait_group %0;" :: "n"(N));
}

// ---------------- prep: fp32 -> fp16 elementwise (x -> xr) -------------------
__global__ void __launch_bounds__(256)
f2h_k(const float* __restrict__ in, __half* __restrict__ out, int n4)
{
    int i = blockIdx.x * 256 + threadIdx.x;
    if (i >= n4) return;
    float4 v = ((const float4*)in)[i];
    ((__half2*)out)[2*i]     = __floats2half2_rn(v.x, v.y);
    ((__half2*)out)[2*i + 1] = __floats2half2_rn(v.z, v.w);
}

// ---------------- prep: transpose + convert weight W[K][N] -> WT[N][K] fp16 --
__global__ void __launch_bounds__(256)
wt_k(const float* __restrict__ W, __half* __restrict__ WT, int K, int N)
{
    __shared__ float t[32][33];
    const int tx = threadIdx.x & 31, ty = threadIdx.x >> 5;   // 32 x 8
    const int n0 = blockIdx.x * 32, k0 = blockIdx.y * 32;
#pragma unroll
    for (int j = 0; j < 4; j++)
        t[ty + j * 8][tx] = W[(long long)(k0 + ty + j * 8) * N + n0 + tx];
    __syncthreads();
#pragma unroll
    for (int j = 0; j < 4; j++)
        WT[(long long)(n0 + ty + j * 8) * K + k0 + tx] = __float2half(t[tx][ty + j * 8]);
}

// ---------------- fp16 tensor-core GEMM, 3-stage cp.async pipeline -----------
// C[m,n] = scale * sum_k A[m,k] * BT[n,k]   (A fp16 [M][K], BT fp16 [N][K])
#define HSTR 72
#define HTSZ (128 * HSTR)
#define HSTG (2 * HTSZ)
#define GEMM_SMEM (3 * HSTG * 2)

template<int EPI>
__global__ void __launch_bounds__(256, 2)
tgemm_h(const __half* __restrict__ A, const __half* __restrict__ BT,
        void* __restrict__ Cv, int N, int K,
        int lda, int ldb, int ldc,
        float scale, const float* __restrict__ bias,
        const float* __restrict__ resid)
{
    extern __shared__ __half hsm[];
    const int tid  = threadIdx.x;
    const int lane = tid & 31;
    const int wid  = tid >> 5;
    const int wm   = wid >> 2;
    const int wn   = wid & 3;
    const int gid  = lane >> 2;
    const int tig  = lane & 3;

    const int row0 = blockIdx.y * 128;
    const int col0 = blockIdx.x * 128;

    int rw[4], sg[4];
#pragma unroll
    for (int i = 0; i < 4; i++) {
        int f = tid + i * 256;
        rw[i] = f >> 3;
        sg[i] = (f & 7) * 8;
    }

    const uint32_t smb = (uint32_t)__cvta_generic_to_shared(hsm);
    const int nkt = K >> 6;

    auto issue = [&](int kt) {
        const int buf = kt % 3;
        const uint32_t as = smb + (uint32_t)(buf * HSTG) * 2u;
        const uint32_t bs = as + (uint32_t)HTSZ * 2u;
        const int k0 = kt * 64;
#pragma unroll
        for (int i = 0; i < 4; i++) {
            cp16(as + (uint32_t)(rw[i] * HSTR + sg[i]) * 2u,
                 &A[(long long)(row0 + rw[i]) * lda + k0 + sg[i]]);
            cp16(bs + (uint32_t)(rw[i] * HSTR + sg[i]) * 2u,
                 &BT[(long long)(col0 + rw[i]) * ldb + k0 + sg[i]]);
        }
        cp_commit();
    };

    issue(0); issue(1);

    float acc[4][4][4];
#pragma unroll
    for (int mi = 0; mi < 4; mi++)
#pragma unroll
        for (int ni = 0; ni < 4; ni++)
#pragma unroll
            for (int r = 0; r < 4; r++) acc[mi][ni][r] = 0.f;

    for (int kt = 0; kt < nkt; kt++) {
        if (kt + 1 < nkt) cp_wait<1>();
        else              cp_wait<0>();
        __syncthreads();

        const uint32_t* Asu = (const uint32_t*)(hsm + (kt % 3) * HSTG);
        const uint32_t* Bsu = Asu + HTSZ / 2;
#pragma unroll
        for (int kg = 0; kg < 4; kg++) {
            const int kw = kg * 8;
            uint32_t af[4][4], bf[4][2];
#pragma unroll
            for (int mi = 0; mi < 4; mi++) {
                int m = wm * 64 + mi * 16 + gid;
                af[mi][0] = Asu[m * 36 + kw + tig];
                af[mi][1] = Asu[(m + 8) * 36 + kw + tig];
                af[mi][2] = Asu[m * 36 + kw + tig + 4];
                af[mi][3] = Asu[(m + 8) * 36 + kw + tig + 4];
            }
#pragma unroll
            for (int ni = 0; ni < 4; ni++) {
                int n = wn * 32 + ni * 8 + gid;
                bf[ni][0] = Bsu[n * 36 + kw + tig];
                bf[ni][1] = Bsu[n * 36 + kw + tig + 4];
            }
#pragma unroll
            for (int mi = 0; mi < 4; mi++)
#pragma unroll
                for (int ni = 0; ni < 4; ni++)
                    mma_f16(acc[mi][ni][0], acc[mi][ni][1], acc[mi][ni][2], acc[mi][ni][3],
                            af[mi][0], af[mi][1], af[mi][2], af[mi][3],
                            bf[ni][0], bf[ni][1]);
        }
        if (kt + 2 < nkt) issue(kt + 2);
    }

    // ---- epilogue ----
#pragma unroll
    for (int mi = 0; mi < 4; mi++) {
#pragma unroll
        for (int ni = 0; ni < 4; ni++) {
            int r0 = row0 + wm * 64 + mi * 16 + gid;
            int cb = col0 + wn * 32 + ni * 8 + tig * 2;
#pragma unroll
            for (int half_ = 0; half_ < 2; half_++) {
                int rr = r0 + half_ * 8;
                float v0 = acc[mi][ni][half_ * 2 + 0] * scale;
                float v1 = acc[mi][ni][half_ * 2 + 1] * scale;
                if (EPI & EPI_BIAS)  { v0 += bias[cb]; v1 += bias[cb + 1]; }
                if (EPI & EPI_RESID) {
                    const float2 rv = *(const float2*)&resid[(long long)rr * ldc + cb];
                    v0 += rv.x; v1 += rv.y;
                }
                if (EPI & EPI_RELU)  { v0 = fmaxf(v0, 0.f); v1 = fmaxf(v1, 0.f); }
                if (EPI & EPI_HALFOUT) {
                    *(__half2*)&((__half*)Cv)[(long long)rr * ldc + cb] = __floats2half2_rn(v0, v1);
                } else {
                    *(float2*)&((float*)Cv)[(long long)rr * ldc + cb] = make_float2(v0, v1);
                }
            }
        }
    }
}

// ---------------- fused flash attention, all-fp16 MMA ------------------------
// CTA: 128 queries of one (b,h). 8 warps x 16 query rows. KV tiles of 64 keys.
// smem (halves): Qs 128x72 | Ks 64x72 | Vt 64x72 (transposed) | Ps 128x72
#define FA_SMEM ((128*72 + 64*72 + 64*72 + 128*72) * 2 + 256)

__global__ void __launch_bounds__(256, 2)
fa_k(const __half* __restrict__ Q, const __half* __restrict__ K,
     const __half* __restrict__ V, const int* __restrict__ mask,
     __half* __restrict__ O)
{
    extern __shared__ __half hsm[];
    __half* Qs = hsm;                       // 128*72
    __half* Ks = Qs + 128 * 72;             // 64*72  [key][dim]
    __half* Vt = Ks + 64 * 72;              // 64*72  [dim][key]  (transposed)
    __half* Ps = Vt + 64 * 72;              // 128*72 [query][key]
    int*    Ms = (int*)(Ps + 128 * 72);     // 64

    const int qt  = blockIdx.x;
    const int z   = blockIdx.y;
    const int b   = z >> 4, h = z & 15;
    const int tid = threadIdx.x, lane = tid & 31, w = tid >> 5;
    const int gid = lane >> 2, tig = lane & 3;

    const long long base = ((long long)b * SS) * D_MODEL + h * DK;
    const __half* Qg = Q + base + (long long)qt * 128 * D_MODEL;
    const __half* Kg = K + base;
    const __half* Vg = V + base;
    const int*    mg = mask + (long long)b * SS;

    // ---- load Q tile (128 x 64 halves = 1024 uint4) ----
#pragma unroll
    for (int i = 0; i < 4; i++) {
        int idx = tid + i * 256;
        int r = idx >> 3, c = (idx & 7) * 8;
        *(uint4*)&Qs[r * 72 + c] = *(const uint4*)&Qg[(long long)r * D_MODEL + c];
    }

    float m0 = -INFINITY, m1 = -INFINITY;
    float l0 = 0.f, l1 = 0.f;
    float oacc[8][4];
#pragma unroll
    for (int ng = 0; ng < 8; ng++)
#pragma unroll
        for (int r = 0; r < 4; r++) oacc[ng][r] = 0.f;

    const uint32_t* Qw = (const uint32_t*)Qs;
    const uint32_t* Kw = (const uint32_t*)Ks;
    const uint32_t* Vw = (const uint32_t*)Vt;
    const uint32_t* Pw = (const uint32_t*)Ps;
    const int qrow = w * 16 + gid;

    for (int kt = 0; kt < SS / 64; kt++) {
        __syncthreads();                    // prev tile consumed
        // ---- load K (straight) + V (transposed) tiles: 2 uint4 each/thread --
#pragma unroll
        for (int i = 0; i < 2; i++) {
            int idx = tid + i * 256;        // 0..511
            int r = idx >> 3, c = (idx & 7) * 8;
            long long go = (long long)(kt * 64 + r) * D_MODEL + c;
            *(uint4*)&Ks[r * 72 + c] = *(const uint4*)&Kg[go];
            uint4 vv = *(const uint4*)&Vg[go];
            const __half* hp = (const __half*)&vv;
#pragma unroll
            for (int j = 0; j < 8; j++)
                Vt[(c + j) * 72 + r] = hp[j];
        }
        if (tid < 64) Ms[tid] = mg[kt * 64 + tid];
        __syncthreads();

        // ---- S = Q @ K^T : per warp m16 x n64, k64 (4 k-steps of 16) ----
        float s[8][4];
#pragma unroll
        for (int ni = 0; ni < 8; ni++)
#pragma unroll
            for (int r = 0; r < 4; r++) s[ni][r] = 0.f;

#pragma unroll
        for (int kg = 0; kg < 4; kg++) {
            const int kw = kg * 8;
            uint32_t a0 = Qw[qrow * 36 + kw + tig];
            uint32_t a1 = Qw[(qrow + 8) * 36 + kw + tig];
            uint32_t a2 = Qw[qrow * 36 + kw + tig + 4];
            uint32_t a3 = Qw[(qrow + 8) * 36 + kw + tig + 4];
#pragma unroll
            for (int ni = 0; ni < 8; ni++) {
                int n = ni * 8 + gid;
                uint32_t b0 = Kw[n * 36 + kw + tig];
                uint32_t b1 = Kw[n * 36 + kw + tig + 4];
                mma_f16(s[ni][0], s[ni][1], s[ni][2], s[ni][3], a0, a1, a2, a3, b0, b1);
            }
        }

        // ---- mask + tile row max ----
        float tm0 = -3.0e38f, tm1 = -3.0e38f;
#pragma unroll
        for (int ni = 0; ni < 8; ni++) {
            int c0 = ni * 8 + tig * 2;
            if (Ms[c0] == 0)     { s[ni][0] = NEGV; s[ni][2] = NEGV; }
            if (Ms[c0 + 1] == 0) { s[ni][1] = NEGV; s[ni][3] = NEGV; }
            tm0 = fmaxf(tm0, fmaxf(s[ni][0], s[ni][1]));
            tm1 = fmaxf(tm1, fmaxf(s[ni][2], s[ni][3]));
        }
        tm0 = fmaxf(tm0, __shfl_xor_sync(0xffffffffu, tm0, 1));
        tm0 = fmaxf(tm0, __shfl_xor_sync(0xffffffffu, tm0, 2));
        tm1 = fmaxf(tm1, __shfl_xor_sync(0xffffffffu, tm1, 1));
        tm1 = fmaxf(tm1, __shfl_xor_sync(0xffffffffu, tm1, 2));

        float mn0 = fmaxf(m0, tm0), mn1 = fmaxf(m1, tm1);
        float cr0 = __expf(m0 - mn0), cr1 = __expf(m1 - mn1);

        // ---- exp + row sums + write P (fp16, warp-private rows) ----
        float sum0 = 0.f, sum1 = 0.f;
#pragma unroll
        for (int ni = 0; ni < 8; ni++) {
            float p0 = __expf(s[ni][0] - mn0);
            float p1 = __expf(s[ni][1] - mn0);
            float p2 = __expf(s[ni][2] - mn1);
            float p3 = __expf(s[ni][3] - mn1);
            sum0 += p0 + p1; sum1 += p2 + p3;
            int c0 = ni * 8 + tig * 2;
            *(__half2*)&Ps[qrow * 72 + c0]       = __floats2half2_rn(p0, p1);
            *(__half2*)&Ps[(qrow + 8) * 72 + c0] = __floats2half2_rn(p2, p3);
        }
        sum0 += __shfl_xor_sync(0xffffffffu, sum0, 1);
        sum0 += __shfl_xor_sync(0xffffffffu, sum0, 2);
        sum1 += __shfl_xor_sync(0xffffffffu, sum1, 1);
        sum1 += __shfl_xor_sync(0xffffffffu, sum1, 2);

        l0 = l0 * cr0 + sum0;
        l1 = l1 * cr1 + sum1;
        m0 = mn0; m1 = mn1;

#pragma unroll
        for (int ng = 0; ng < 8; ng++) {
            oacc[ng][0] *= cr0; oacc[ng][1] *= cr0;
            oacc[ng][2] *= cr1; oacc[ng][3] *= cr1;
        }
        __syncwarp();

        // ---- O += P @ V : m16 x n64(dims), k64(keys) ----
#pragma unroll
        for (int kg = 0; kg < 4; kg++) {
            const int kw = kg * 8;
            uint32_t a0 = Pw[qrow * 36 + kw + tig];
            uint32_t a1 = Pw[(qrow + 8) * 36 + kw + tig];
            uint32_t a2 = Pw[qrow * 36 + kw + tig + 4];
            uint32_t a3 = Pw[(qrow + 8) * 36 + kw + tig + 4];
#pragma unroll
            for (int ng = 0; ng < 8; ng++) {
                int n = ng * 8 + gid;
                uint32_t b0 = Vw[n * 36 + kw + tig];
                uint32_t b1 = Vw[n * 36 + kw + tig + 4];
                mma_f16(oacc[ng][0], oacc[ng][1], oacc[ng][2], oacc[ng][3],
                        a0, a1, a2, a3, b0, b1);
            }
        }
    }

    // ---- normalize & write ctx (fp16) ----
    float inv0 = 1.0f / l0, inv1 = 1.0f / l1;
    __half* Og = O + base + (long long)qt * 128 * D_MODEL;
#pragma unroll
    for (int ng = 0; ng < 8; ng++) {
        int c = ng * 8 + tig * 2;
        *(__half2*)&Og[(long long)qrow * D_MODEL + c] =
            __floats2half2_rn(oacc[ng][0] * inv0, oacc[ng][1] * inv0);
        *(__half2*)&Og[(long long)(qrow + 8) * D_MODEL + c] =
            __floats2half2_rn(oacc[ng][2] * inv1, oacc[ng][3] * inv1);
    }
}

// ---------------- LayerNorm (ddof=1, /(std+eps)) -----------------------------
template<int WH>
__global__ void __launch_bounds__(256)
ln_k(const float* __restrict__ in, float* __restrict__ out,
     __half* __restrict__ outh,
     const float* __restrict__ alpha, const float* __restrict__ beta)
{
    const long long row = blockIdx.x;
    const float* p = in + row * D_MODEL;
    const int tid = threadIdx.x;

    float4 x4 = ((const float4*)p)[tid];
    float s  = x4.x + x4.y + x4.z + x4.w;
    float sq = x4.x*x4.x + x4.y*x4.y + x4.z*x4.z + x4.w*x4.w;

    __shared__ float rs[256], rq[256];
    rs[tid] = s; rq[tid] = sq; __syncthreads();
    for (int st = 128; st > 0; st >>= 1) {
        if (tid < st) { rs[tid] += rs[tid + st]; rq[tid] += rq[tid + st]; }
        __syncthreads();
    }
    float mean = rs[0] * (1.0f / D_MODEL);
    float var  = (rq[0] - rs[0] * mean) * (1.0f / (D_MODEL - 1));
    var = fmaxf(var, 0.f);
    float inv = 1.0f / (sqrtf(var) + LN_EPS);

    float4 a4 = ((const float4*)alpha)[tid];
    float4 b4 = ((const float4*)beta)[tid];
    float4 o4;
    o4.x = a4.x * (x4.x - mean) * inv + b4.x;
    o4.y = a4.y * (x4.y - mean) * inv + b4.y;
    o4.z = a4.z * (x4.z - mean) * inv + b4.z;
    o4.w = a4.w * (x4.w - mean) * inv + b4.w;
    ((float4*)(out + row * D_MODEL))[tid] = o4;
    if (WH) {
        __half2* oh = (__half2*)(outh + row * D_MODEL);
        oh[tid * 2]     = __floats2half2_rn(o4.x, o4.y);
        oh[tid * 2 + 1] = __floats2half2_rn(o4.z, o4.w);
    }
}

// ---------------- launcher ---------------------------------------------------
extern "C" void kernel_launch(void* const* d_in, const int* in_sizes, int n_in,
                              void* d_out, int out_size)
{
    const float* x     = (const float*)d_in[0];
    const int*   mask  = (const int*)  d_in[1];
    const float* w_q   = (const float*)d_in[2];
    const float* w_k   = (const float*)d_in[3];
    const float* w_v   = (const float*)d_in[4];
    const float* w_o   = (const float*)d_in[5];
    const float* W1    = (const float*)d_in[6];
    const float* b1    = (const float*)d_in[7];
    const float* W2    = (const float*)d_in[8];
    const float* b2    = (const float*)d_in[9];
    const float* al1   = (const float*)d_in[10];
    const float* be1   = (const float*)d_in[11];
    const float* al2   = (const float*)d_in[12];
    const float* be2   = (const float*)d_in[13];
    float* out = (float*)d_out;

    float *T1, *X1F, *T2;
    __half *Q, *Kb, *V, *CTX, *X1H, *H, *XR, *WQT, *WKT, *WVT, *WOT, *W1T, *W2T;
    cudaGetSymbolAddress((void**)&Q,   g_Q);
    cudaGetSymbolAddress((void**)&Kb,  g_Kb);
    cudaGetSymbolAddress((void**)&V,   g_V);
    cudaGetSymbolAddress((void**)&CTX, g_ctx);
    cudaGetSymbolAddress((void**)&T1,  g_t1);
    cudaGetSymbolAddress((void**)&X1H, g_x1h);
    cudaGetSymbolAddress((void**)&X1F, g_x1f);
    cudaGetSymbolAddress((void**)&H,   g_h);
    cudaGetSymbolAddress((void**)&T2,  g_t2);
    cudaGetSymbolAddress((void**)&XR,  g_xr);
    cudaGetSymbolAddress((void**)&WQT, g_wqt);
    cudaGetSymbolAddress((void**)&WKT, g_wkt);
    cudaGetSymbolAddress((void**)&WVT, g_wvt);
    cudaGetSymbolAddress((void**)&WOT, g_wot);
    cudaGetSymbolAddress((void**)&W1T, g_W1t);
    cudaGetSymbolAddress((void**)&W2T, g_W2t);

    cudaFuncSetAttribute(fa_k, cudaFuncAttributeMaxDynamicSharedMemorySize, FA_SMEM);
    cudaFuncSetAttribute(tgemm_h<EPI_HALFOUT>, cudaFuncAttributeMaxDynamicSharedMemorySize, GEMM_SMEM);
    cudaFuncSetAttribute(tgemm_h<EPI_RESID>, cudaFuncAttributeMaxDynamicSharedMemorySize, GEMM_SMEM);
    cudaFuncSetAttribute(tgemm_h<EPI_BIAS|EPI_RELU|EPI_HALFOUT>, cudaFuncAttributeMaxDynamicSharedMemorySize, GEMM_SMEM);
    cudaFuncSetAttribute(tgemm_h<EPI_BIAS|EPI_RESID>, cudaFuncAttributeMaxDynamicSharedMemorySize, GEMM_SMEM);

    const dim3 blk(256);
    auto grd = [](int N, int M) {
        return dim3((unsigned)(N / 128), (unsigned)(M / 128), 1);
    };

    // 0: operand prep — x to fp16; weights transposed+fp16
    f2h_k<<<(NTOK * D_MODEL / 4 + 255) / 256, blk>>>(x, XR, NTOK * D_MODEL / 4);
    wt_k<<<dim3(32, 32), blk>>>(w_q, WQT, D_MODEL, D_MODEL);
    wt_k<<<dim3(32, 32), blk>>>(w_k, WKT, D_MODEL, D_MODEL);
    wt_k<<<dim3(32, 32), blk>>>(w_v, WVT, D_MODEL, D_MODEL);
    wt_k<<<dim3(32, 32), blk>>>(w_o, WOT, D_MODEL, D_MODEL);
    wt_k<<<dim3(128, 32), blk>>>(W1, W1T, D_MODEL, D_FF);
    wt_k<<<dim3(32, 128), blk>>>(W2, W2T, D_FF, D_MODEL);

    // 1-3: Q/K/V projections -> fp16 (Q pre-scaled by 1/8)
    tgemm_h<EPI_HALFOUT><<<grd(D_MODEL, NTOK), blk, GEMM_SMEM>>>(XR, WQT, Q, D_MODEL, D_MODEL,
        D_MODEL, D_MODEL, D_MODEL, 0.125f, nullptr, nullptr);
    tgemm_h<EPI_HALFOUT><<<grd(D_MODEL, NTOK), blk, GEMM_SMEM>>>(XR, WKT, Kb, D_MODEL, D_MODEL,
        D_MODEL, D_MODEL, D_MODEL, 1.f, nullptr, nullptr);
    tgemm_h<EPI_HALFOUT><<<grd(D_MODEL, NTOK), blk, GEMM_SMEM>>>(XR, WVT, V, D_MODEL, D_MODEL,
        D_MODEL, D_MODEL, D_MODEL, 1.f, nullptr, nullptr);

    // 4: fused attention (all fp16 MMA) -> ctx (fp16)
    fa_k<<<dim3(SS / 128, BB * HEADS), blk, FA_SMEM>>>(Q, Kb, V, mask, CTX);

    // 5: t1 = ctx @ w_o + x  (fp32 out)
    tgemm_h<EPI_RESID><<<grd(D_MODEL, NTOK), blk, GEMM_SMEM>>>(CTX, WOT, T1, D_MODEL, D_MODEL,
        D_MODEL, D_MODEL, D_MODEL, 1.f, nullptr, x);

    // 6: x1 = LN1(t1) -> fp32 (residual) + fp16 (GEMM operand)
    ln_k<1><<<NTOK, blk>>>(T1, X1F, X1H, al1, be1);

    // 7: h = relu(x1 @ W1 + b1) -> fp16
    tgemm_h<EPI_BIAS|EPI_RELU|EPI_HALFOUT><<<grd(D_FF, NTOK), blk, GEMM_SMEM>>>(X1H, W1T, H,
        D_FF, D_MODEL, D_MODEL, D_MODEL, D_FF, 1.f, b1, nullptr);

    // 8: t2 = h @ W2 + b2 + x1  (fp32 out)
    tgemm_h<EPI_BIAS|EPI_RESID><<<grd(D_MODEL, NTOK), blk, GEMM_SMEM>>>(H, W2T, T2,
        D_MODEL, D_FF, D_FF, D_FF, D_MODEL, 1.f, b2, X1F);

    // 9: out = LN2(t2), full fp32
    ln_k<0><<<NTOK, blk>>>(T2, out, nullptr, al2, be2);
}